// round 1
// baseline (speedup 1.0000x reference)
#include <cuda_runtime.h>
#include <math.h>
#include <float.h>
#include <stdint.h>

// Problem constants
#define BB 4
#define TT 8192
#define SS 4096
#define DD 256
#define GG 512
#define HH 256
#define KK 8
#define ROWS (BB*TT)        // 32768
#define NIP 771
#define NIPAD 784           // padded K for GEMM1 (multiple of 16)
#define N1 640              // 256 (W1) + 256 (Ws) + 128 (M1)
#define N2 320              // 256 (h2) + 64 (m2)

// ---------------- scratch (device globals; no allocation) ----------------
__device__ int   g_idx[ROWS * KK];
__device__ float g_d2 [ROWS * KK];
__device__ float g_ni [ (size_t)ROWS * NIPAD ];   // ~103 MB
__device__ float g_wcat[ NIPAD * N1 ];            // packed [W1|Ws|M1], zero-padded rows
__device__ float g_bias1[ N1 ];
__device__ float g_y1 [ (size_t)ROWS * N1 ];      // ~84 MB  : [h1 | s | m1]
__device__ float g_y2 [ (size_t)ROWS * N2 ];      // ~42 MB  : [h2 | m2]

// ---------------- KNN: top-8 nearest surf points per template point ------
// grid (T/128, B), block 128.  Surf tiled through SMEM in 2 chunks of 2048.
__global__ void knn_kernel(const float* __restrict__ tmpl,
                           const float* __restrict__ surf)
{
    __shared__ float4 ss[2048];   // 32 KB
    const int b   = blockIdx.y;
    const int t   = blockIdx.x * 128 + threadIdx.x;
    const int row = b * TT + t;

    const float tx = tmpl[row*3+0];
    const float ty = tmpl[row*3+1];
    const float tz = tmpl[row*3+2];

    float bd[KK]; int bi[KK];
#pragma unroll
    for (int q = 0; q < KK; q++) { bd[q] = FLT_MAX; bi[q] = 0; }

    const float* sb = surf + (size_t)b * SS * 3;

    for (int tile = 0; tile < 2; tile++) {
        __syncthreads();
        for (int i = threadIdx.x; i < 2048; i += 128) {
            int sp = tile * 2048 + i;
            ss[i] = make_float4(sb[sp*3+0], sb[sp*3+1], sb[sp*3+2], 0.f);
        }
        __syncthreads();

#pragma unroll 4
        for (int j = 0; j < 2048; j++) {
            float4 p = ss[j];
            float dx = tx - p.x, dy = ty - p.y, dz = tz - p.z;
            float d2 = fmaf(dx, dx, fmaf(dy, dy, dz*dz));
            if (d2 < bd[KK-1]) {
                float v = d2; int vi = tile * 2048 + j;
#pragma unroll
                for (int q = 0; q < KK; q++) {
                    if (v < bd[q]) {
                        float tv = bd[q]; int ti = bi[q];
                        bd[q] = v; bi[q] = vi;
                        v = tv; vi = ti;
                    }
                }
            }
        }
    }
#pragma unroll
    for (int q = 0; q < KK; q++) {
        g_d2 [row*KK+q] = bd[q];
        g_idx[row*KK+q] = bi[q];
    }
}

// ---------------- pack [W1 | Ws | M1] into g_wcat (K padded to 784) ------
__global__ void prepack_kernel(const float* __restrict__ W1,
                               const float* __restrict__ Ws,
                               const float* __restrict__ M1,
                               const float* __restrict__ b1,
                               const float* __restrict__ bs,
                               const float* __restrict__ mb1)
{
    int idx = blockIdx.x * 256 + threadIdx.x;
    if (idx < NIPAD * N1) {
        int k = idx / N1, n = idx % N1;
        float v = 0.f;
        if (k < NIP) {
            if (n < 256)       v = W1[k*256 + n];
            else if (n < 512)  v = Ws[k*256 + (n-256)];
            else               v = M1[k*128 + (n-512)];
        }
        g_wcat[idx] = v;
    }
    if (idx < N1) {
        float bv;
        if (idx < 256)       bv = b1[idx];
        else if (idx < 512)  bv = bs[idx-256];
        else                 bv = mb1[idx-512];
        g_bias1[idx] = bv;
    }
}

// ---------------- build ni = [template | local | global], padded ---------
// grid ROWS, block 256 (= D).
__global__ void build_ni_kernel(const float* __restrict__ tmpl,
                                const float* __restrict__ gfeat,
                                const float* __restrict__ pfeat)
{
    const int row = blockIdx.x;
    const int tid = threadIdx.x;
    const int b   = row >> 13;   // row / T

    float w[KK]; int id[KK]; float wsum = 0.f;
#pragma unroll
    for (int k = 0; k < KK; k++) {
        id[k] = g_idx[row*KK+k];
        float d = sqrtf(g_d2[row*KK+k]);
        w[k] = 1.f / (d + 1e-8f);
        wsum += w[k];
    }
    float inv = 1.f / wsum;
#pragma unroll
    for (int k = 0; k < KK; k++) w[k] *= inv;

    const float* pfb = pfeat + (size_t)b * SS * DD;
    float acc = 0.f;
#pragma unroll
    for (int k = 0; k < KK; k++)
        acc = fmaf(w[k], pfb[(size_t)id[k]*DD + tid], acc);

    float* nrow = g_ni + (size_t)row * NIPAD;
    nrow[3 + tid]       = acc;                       // local features
    nrow[259 + tid]     = gfeat[b*GG + tid];         // global 0..255
    nrow[259 + 256 + tid] = gfeat[b*GG + 256 + tid]; // global 256..511
    if (tid < 3)  nrow[tid] = tmpl[row*3 + tid];
    if (tid < NIPAD - NIP) nrow[NIP + tid] = 0.f;    // zero pad
}

// ---------------- generic tiled SGEMM with fused epilogues ---------------
// MODE 0: Y1 = ni @ Wcat       (+bias, relu on cols [0,256)&[512,640))
// MODE 1: h2 = relu(h1@W2+b2) + s         -> g_y2 cols [0,256)
// MODE 2: m2 = relu(m1@M2+mb2)            -> g_y2 cols [256,320)
template<int BM, int BN, int BK, int TM, int TN, int MODE>
__global__ void gemm_kernel(const float* __restrict__ Bext,
                            const float* __restrict__ biasext)
{
    constexpr int THREADS = (BM/TM) * (BN/TN);
    constexpr int KTOT = (MODE == 0) ? NIPAD : ((MODE == 1) ? 256 : 128);
    constexpr int TILES = KTOT / BK;
    constexpr int NA = (BM*BK/4) / THREADS;
    constexpr int NB = (BK*BN/4) / THREADS;

    const float* A; int lda; const float* Bm; int ldb;
    float* C; int ldc; const float* bias;
    if (MODE == 0) { A = g_ni;        lda = NIPAD; Bm = g_wcat; ldb = N1;  C = g_y1;        ldc = N1; bias = g_bias1; }
    else if (MODE == 1) { A = g_y1;   lda = N1;    Bm = Bext;   ldb = 256; C = g_y2;        ldc = N2; bias = biasext; }
    else { A = g_y1 + 512;            lda = N1;    Bm = Bext;   ldb = 64;  C = g_y2 + 256;  ldc = N2; bias = biasext; }

    __shared__ __align__(16) float As[BK*BM];
    __shared__ __align__(16) float Bs[BK*BN];

    const int tid  = threadIdx.x;
    const int row0 = blockIdx.y * BM;
    const int n0   = blockIdx.x * BN;
    const int tm0  = (tid / (BN/TN)) * TM;
    const int tn0  = (tid % (BN/TN)) * TN;

    float4 pa[NA], pb[NB];

    auto loadg = [&](int k0) {
#pragma unroll
        for (int i = 0; i < NA; i++) {
            int idx = tid + i*THREADS; int m = idx / (BK/4); int kv = idx % (BK/4);
            pa[i] = *(const float4*)(A + (size_t)(row0+m)*lda + k0 + kv*4);
        }
#pragma unroll
        for (int i = 0; i < NB; i++) {
            int idx = tid + i*THREADS; int kr = idx / (BN/4); int nv = idx % (BN/4);
            pb[i] = *(const float4*)(Bm + (size_t)(k0+kr)*ldb + n0 + nv*4);
        }
    };
    auto stage = [&]() {
#pragma unroll
        for (int i = 0; i < NA; i++) {
            int idx = tid + i*THREADS; int m = idx / (BK/4); int kv = idx % (BK/4);
            As[(kv*4+0)*BM + m] = pa[i].x;
            As[(kv*4+1)*BM + m] = pa[i].y;
            As[(kv*4+2)*BM + m] = pa[i].z;
            As[(kv*4+3)*BM + m] = pa[i].w;
        }
#pragma unroll
        for (int i = 0; i < NB; i++) {
            int idx = tid + i*THREADS; int kr = idx / (BN/4); int nv = idx % (BN/4);
            *(float4*)&Bs[kr*BN + nv*4] = pb[i];
        }
    };

    float acc[TM][TN];
#pragma unroll
    for (int i = 0; i < TM; i++)
#pragma unroll
        for (int j = 0; j < TN; j++) acc[i][j] = 0.f;

    loadg(0);
#pragma unroll 1
    for (int t = 0; t < TILES; t++) {
        __syncthreads();
        stage();
        __syncthreads();
        if (t + 1 < TILES) loadg((t+1) * BK);
#pragma unroll
        for (int kk = 0; kk < BK; kk++) {
            float af[TM], bf[TN];
#pragma unroll
            for (int i = 0; i < TM/4; i++)
                *(float4*)&af[i*4] = *(const float4*)&As[kk*BM + tm0 + i*4];
#pragma unroll
            for (int j = 0; j < TN/4; j++)
                *(float4*)&bf[j*4] = *(const float4*)&Bs[kk*BN + tn0 + j*4];
#pragma unroll
            for (int i = 0; i < TM; i++)
#pragma unroll
                for (int j = 0; j < TN; j++)
                    acc[i][j] = fmaf(af[i], bf[j], acc[i][j]);
        }
    }

#pragma unroll
    for (int i = 0; i < TM; i++) {
        int r = row0 + tm0 + i;
#pragma unroll
        for (int j = 0; j < TN; j++) {
            int n = n0 + tn0 + j;
            float v = acc[i][j] + bias[n];
            if (MODE == 0) {
                if (n < 256 || n >= 512) v = fmaxf(v, 0.f);
            } else if (MODE == 1) {
                v = fmaxf(v, 0.f) + g_y1[(size_t)r*N1 + 256 + n];
            } else {
                v = fmaxf(v, 0.f);
            }
            C[(size_t)r*ldc + n] = v;
        }
    }
}

// ---------------- heads: disp = (h2@Wo + bo)*0.3 ; mat = sigmoid(m2@M3+mb3)
// one warp per row, 8 rows per block.
__global__ void head_kernel(const float* __restrict__ Wo,
                            const float* __restrict__ bo,
                            const float* __restrict__ M3,
                            const float* __restrict__ mb3,
                            float* __restrict__ out)
{
    const int row  = blockIdx.x * 8 + (threadIdx.x >> 5);
    const int lane = threadIdx.x & 31;
    const float* y = g_y2 + (size_t)row * N2;

    float a0 = 0.f, a1 = 0.f, a2 = 0.f, am = 0.f;
#pragma unroll
    for (int c = lane; c < 256; c += 32) {
        float h = y[c];
        a0 = fmaf(h, Wo[c*3+0], a0);
        a1 = fmaf(h, Wo[c*3+1], a1);
        a2 = fmaf(h, Wo[c*3+2], a2);
    }
#pragma unroll
    for (int c = lane; c < 64; c += 32)
        am = fmaf(y[256+c], M3[c], am);

#pragma unroll
    for (int o = 16; o > 0; o >>= 1) {
        a0 += __shfl_xor_sync(0xffffffffu, a0, o);
        a1 += __shfl_xor_sync(0xffffffffu, a1, o);
        a2 += __shfl_xor_sync(0xffffffffu, a2, o);
        am += __shfl_xor_sync(0xffffffffu, am, o);
    }
    if (lane == 0) {
        out[row*3+0] = (a0 + bo[0]) * 0.3f;
        out[row*3+1] = (a1 + bo[1]) * 0.3f;
        out[row*3+2] = (a2 + bo[2]) * 0.3f;
        float x = am + mb3[0];
        out[ROWS*3 + row] = 1.f / (1.f + expf(-x));
    }
}

// --------------------------------- launch --------------------------------
extern "C" void kernel_launch(void* const* d_in, const int* in_sizes, int n_in,
                              void* d_out, int out_size)
{
    const float* tmpl  = (const float*)d_in[0];
    const float* surf  = (const float*)d_in[1];
    const float* gfeat = (const float*)d_in[2];
    const float* pfeat = (const float*)d_in[3];
    const float* W1 = (const float*)d_in[4];
    const float* b1 = (const float*)d_in[5];
    const float* W2 = (const float*)d_in[6];
    const float* b2 = (const float*)d_in[7];
    const float* Ws = (const float*)d_in[8];
    const float* bs = (const float*)d_in[9];
    const float* Wo = (const float*)d_in[10];
    const float* bo = (const float*)d_in[11];
    const float* M1 = (const float*)d_in[12];
    const float* mb1 = (const float*)d_in[13];
    const float* M2 = (const float*)d_in[14];
    const float* mb2 = (const float*)d_in[15];
    const float* M3 = (const float*)d_in[16];
    const float* mb3 = (const float*)d_in[17];
    float* out = (float*)d_out;

    knn_kernel<<<dim3(TT/128, BB), 128>>>(tmpl, surf);
    prepack_kernel<<<(NIPAD*N1 + 255)/256, 256>>>(W1, Ws, M1, b1, bs, mb1);
    build_ni_kernel<<<ROWS, 256>>>(tmpl, gfeat, pfeat);

    // GEMM1: [32768 x 784] @ [784 x 640]
    gemm_kernel<128,128,16,8,8,0><<<dim3(N1/128, ROWS/128), 256>>>(nullptr, nullptr);
    // GEMM2a: h2 = relu(h1@W2+b2)+s  [32768 x 256] K=256
    gemm_kernel<128,128,16,8,8,1><<<dim3(256/128, ROWS/128), 256>>>(W2, b2);
    // GEMM2b: m2 = relu(m1@M2+mb2)   [32768 x 64]  K=128
    gemm_kernel<128,64,16,8,4,2><<<dim3(1, ROWS/128), 256>>>(M2, mb2);

    head_kernel<<<ROWS/8, 256>>>(Wo, bo, M3, mb3, out);
}

// round 5
// speedup vs baseline: 1.9343x; 1.9343x over previous
#include <cuda_runtime.h>
#include <cuda_bf16.h>
#include <math.h>
#include <float.h>
#include <stdint.h>

// Problem constants
#define BB 4
#define TT 8192
#define SS 4096
#define DD 256
#define GG 512
#define KK 8
#define ROWS (BB*TT)        // 32768
#define NIP 771
#define KPAD1 832           // 13 * 64
#define N1 640              // 256 (W1) + 256 (Ws) + 128 (M1)
#define N2 320              // 256 (h2) + 64 (m2)

// ---------------- scratch (device globals; no allocation) ----------------
__device__ __align__(128) int   g_idx[ROWS * KK];
__device__ __align__(128) float g_d2 [ROWS * KK];
__device__ __align__(128) __nv_bfloat16 g_ni_hi[(size_t)ROWS * KPAD1];
__device__ __align__(128) __nv_bfloat16 g_ni_lo[(size_t)ROWS * KPAD1];
__device__ __align__(128) __nv_bfloat16 g_w1t_hi[N1 * KPAD1];
__device__ __align__(128) __nv_bfloat16 g_w1t_lo[N1 * KPAD1];
__device__ __align__(128) __nv_bfloat16 g_w2t_hi[256 * 256];
__device__ __align__(128) __nv_bfloat16 g_w2t_lo[256 * 256];
__device__ __align__(128) float g_bias1[N1];
__device__ __align__(128) __nv_bfloat16 g_h1hi[(size_t)ROWS * 256];
__device__ __align__(128) __nv_bfloat16 g_h1lo[(size_t)ROWS * 256];
__device__ __align__(128) float g_s  [(size_t)ROWS * 256];
__device__ __align__(128) float g_m1f[(size_t)ROWS * 128];
__device__ __align__(128) float g_y2 [(size_t)ROWS * N2];

// =================== helpers =============================================
__device__ __forceinline__ uint32_t smem_to_u32(const void* p) {
    uint32_t a;
    asm("{ .reg .u64 t; cvta.to.shared.u64 t, %1; cvt.u32.u64 %0, t; }" : "=r"(a) : "l"(p));
    return a;
}
__device__ __forceinline__ void ldsm4(uint32_t* r, uint32_t addr) {
    asm volatile("ldmatrix.sync.aligned.m8n8.x4.shared.b16 {%0,%1,%2,%3}, [%4];"
        : "=r"(r[0]), "=r"(r[1]), "=r"(r[2]), "=r"(r[3]) : "r"(addr));
}
__device__ __forceinline__ void mma_bf16(float* c, const uint32_t* a, const uint32_t* b) {
    asm volatile("mma.sync.aligned.m16n8k16.row.col.f32.bf16.bf16.f32 "
        "{%0,%1,%2,%3}, {%4,%5,%6,%7}, {%8,%9}, {%0,%1,%2,%3};"
        : "+f"(c[0]), "+f"(c[1]), "+f"(c[2]), "+f"(c[3])
        : "r"(a[0]), "r"(a[1]), "r"(a[2]), "r"(a[3]), "r"(b[0]), "r"(b[1]));
}
#define CP_ASYNC16(dst, src) \
    asm volatile("cp.async.cg.shared.global [%0], [%1], 16;" :: "r"(dst), "l"(src))
#define CP_COMMIT()  asm volatile("cp.async.commit_group;" ::: "memory")
#define CP_WAIT(n)   asm volatile("cp.async.wait_group %0;" :: "n"(n) : "memory")

// swizzle for tiles with 64-byte rows (32 bf16): permute 16B chunk within the
// row by (row>>1)&3 -> all 8 ldmatrix row-addresses distinct mod 128B.
__device__ __forceinline__ uint32_t swz64(uint32_t off) {
    return off ^ (((off >> 7) & 3u) << 4);
}
__device__ __forceinline__ void bf16split(float v, __nv_bfloat16& h, __nv_bfloat16& l) {
    h = __float2bfloat16(v);
    l = __float2bfloat16(v - __bfloat162float(h));
}

// ---------------- KNN: top-8 nearest surf points per template point ------
__global__ void knn_kernel(const float* __restrict__ tmpl,
                           const float* __restrict__ surf)
{
    __shared__ float4 ss[2048];
    const int b   = blockIdx.y;
    const int t   = blockIdx.x * 128 + threadIdx.x;
    const int row = b * TT + t;

    const float tx = tmpl[row*3+0];
    const float ty = tmpl[row*3+1];
    const float tz = tmpl[row*3+2];

    float bd[KK]; int bi[KK];
#pragma unroll
    for (int q = 0; q < KK; q++) { bd[q] = FLT_MAX; bi[q] = 0; }
    const float* sb = surf + (size_t)b * SS * 3;

    for (int tile = 0; tile < 2; tile++) {
        __syncthreads();
        for (int i = threadIdx.x; i < 2048; i += 128) {
            int sp = tile * 2048 + i;
            ss[i] = make_float4(sb[sp*3+0], sb[sp*3+1], sb[sp*3+2], 0.f);
        }
        __syncthreads();
#pragma unroll 4
        for (int j = 0; j < 2048; j++) {
            float4 p = ss[j];
            float dx = tx - p.x, dy = ty - p.y, dz = tz - p.z;
            float d2 = fmaf(dx, dx, fmaf(dy, dy, dz*dz));
            if (d2 < bd[KK-1]) {
                float v = d2; int vi = tile * 2048 + j;
#pragma unroll
                for (int q = 0; q < KK; q++) {
                    if (v < bd[q]) {
                        float tv = bd[q]; int ti = bi[q];
                        bd[q] = v; bi[q] = vi; v = tv; vi = ti;
                    }
                }
            }
        }
    }
#pragma unroll
    for (int q = 0; q < KK; q++) {
        g_d2 [row*KK+q] = bd[q];
        g_idx[row*KK+q] = bi[q];
    }
}

// ---------------- prepack: transpose+split weights to bf16 hi/lo ---------
__global__ void prepack_kernel(const float* __restrict__ W1,
                               const float* __restrict__ Ws,
                               const float* __restrict__ M1,
                               const float* __restrict__ b1,
                               const float* __restrict__ bs,
                               const float* __restrict__ mb1,
                               const float* __restrict__ W2)
{
    int idx = blockIdx.x * 256 + threadIdx.x;
    if (idx < N1 * KPAD1) {
        int n = idx / KPAD1, k = idx % KPAD1;
        float v = 0.f;
        if (k < NIP) {
            if (n < 256)       v = W1[k*256 + n];
            else if (n < 512)  v = Ws[k*256 + (n-256)];
            else               v = M1[k*128 + (n-512)];
        }
        __nv_bfloat16 h, l; bf16split(v, h, l);
        g_w1t_hi[idx] = h; g_w1t_lo[idx] = l;
    }
    if (idx < 256 * 256) {
        int n = idx / 256, k = idx % 256;
        __nv_bfloat16 h, l; bf16split(W2[k*256 + n], h, l);
        g_w2t_hi[idx] = h; g_w2t_lo[idx] = l;
    }
    if (idx < N1) {
        float bv;
        if (idx < 256)       bv = b1[idx];
        else if (idx < 512)  bv = bs[idx-256];
        else                 bv = mb1[idx-512];
        g_bias1[idx] = bv;
    }
}

// ---------------- build ni = [template | local | global] -> bf16 hi/lo ---
__global__ void build_ni_kernel(const float* __restrict__ tmpl,
                                const float* __restrict__ gfeat,
                                const float* __restrict__ pfeat)
{
    const int row = blockIdx.x;
    const int tid = threadIdx.x;
    const int b   = row >> 13;

    float w[KK]; int id[KK]; float wsum = 0.f;
#pragma unroll
    for (int k = 0; k < KK; k++) {
        id[k] = g_idx[row*KK+k];
        float d = sqrtf(g_d2[row*KK+k]);
        w[k] = 1.f / (d + 1e-8f);
        wsum += w[k];
    }
    float inv = 1.f / wsum;
#pragma unroll
    for (int k = 0; k < KK; k++) w[k] *= inv;

    const float* pfb = pfeat + (size_t)b * SS * DD;
    float acc = 0.f;
#pragma unroll
    for (int k = 0; k < KK; k++)
        acc = fmaf(w[k], pfb[(size_t)id[k]*DD + tid], acc);

    __nv_bfloat16* nh = g_ni_hi + (size_t)row * KPAD1;
    __nv_bfloat16* nl = g_ni_lo + (size_t)row * KPAD1;
    __nv_bfloat16 h, l;
    bf16split(acc, h, l); nh[3+tid] = h; nl[3+tid] = l;
    bf16split(gfeat[b*GG + tid], h, l);        nh[259+tid] = h; nl[259+tid] = l;
    bf16split(gfeat[b*GG + 256 + tid], h, l);  nh[515+tid] = h; nl[515+tid] = l;
    if (tid < 3) { bf16split(tmpl[row*3+tid], h, l); nh[tid] = h; nl[tid] = l; }
    if (tid < KPAD1 - NIP) {
        nh[NIP+tid] = __float2bfloat16(0.f);
        nl[NIP+tid] = __float2bfloat16(0.f);
    }
}

// =============== mma.sync compensated bf16 GEMM (128x64, BK=32) ==========
// Static shared memory only: 2 stages x (Ahi 8K + Alo 8K + Bhi 4K + Blo 4K)
// = 48 KB exactly. No dynamic smem, no cudaFuncSetAttribute.
// MODE 0: GEMM1   A=ni (K=832), B=w1t, epilogue -> h1(bf16 hi/lo)/s(f32)/m1(f32)
// MODE 1: GEMM2a  A=h1 (K=256), B=w2t, epilogue -> y2 = relu(.+b2)+s
#define A_TILE_B 8192        // 128 rows x 64 bytes
#define B_TILE_B 4096        // 64 rows x 64 bytes

template<int MODE>
__global__ void __launch_bounds__(256, 1) mma_gemm(const float* __restrict__ biasext)
{
    constexpr int KTOT = (MODE == 0) ? KPAD1 : 256;
    constexpr int NCH  = KTOT / 32;

    __shared__ __align__(128) __nv_bfloat16 sAhi[2][A_TILE_B/2];
    __shared__ __align__(128) __nv_bfloat16 sAlo[2][A_TILE_B/2];
    __shared__ __align__(128) __nv_bfloat16 sBhi[2][B_TILE_B/2];
    __shared__ __align__(128) __nv_bfloat16 sBlo[2][B_TILE_B/2];

    const int tid  = threadIdx.x;
    const int wid  = tid >> 5;
    const int lane = tid & 31;
    const int m0 = blockIdx.y * 128;
    const int n0 = blockIdx.x * 64;

    const __nv_bfloat16 *Ahi, *Alo, *Bhi, *Blo;
    const float* bias;
    if (MODE == 0) { Ahi = g_ni_hi; Alo = g_ni_lo; Bhi = g_w1t_hi; Blo = g_w1t_lo; bias = g_bias1; }
    else           { Ahi = g_h1hi;  Alo = g_h1lo;  Bhi = g_w2t_hi; Blo = g_w2t_lo; bias = biasext; }

    const uint32_t uAhi[2] = { smem_to_u32(sAhi[0]), smem_to_u32(sAhi[1]) };
    const uint32_t uAlo[2] = { smem_to_u32(sAlo[0]), smem_to_u32(sAlo[1]) };
    const uint32_t uBhi[2] = { smem_to_u32(sBhi[0]), smem_to_u32(sBhi[1]) };
    const uint32_t uBlo[2] = { smem_to_u32(sBlo[0]), smem_to_u32(sBlo[1]) };

    const int wm = (wid & 3) * 32;       // warp m-offset (4 row-warps)
    const int wn = (wid >> 2) * 32;      // warp n-offset (2 col-warps)

    float acc[2][4][4];
#pragma unroll
    for (int i = 0; i < 2; i++)
#pragma unroll
        for (int j = 0; j < 4; j++)
#pragma unroll
            for (int q = 0; q < 4; q++) acc[i][j][q] = 0.f;

    // stage loader: A 512+512 chunks, B 256+256 chunks of 16B; 6 per thread
    auto issue_stage = [&](int ch, int buf) {
        const int kc = ch * 32;
#pragma unroll
        for (int t = 0; t < 6; t++) {
            int idx = tid + t * 256;
            if (idx < 1024) {               // A tiles: 2 x 512 chunks
                int half  = idx >> 9;       // 0=hi 1=lo
                int sub   = idx & 511;
                int row   = sub >> 2;
                int chunk = sub & 3;
                const __nv_bfloat16* gp =
                    (half ? Alo : Ahi) + (size_t)(m0 + row) * KTOT + kc + chunk * 8;
                uint32_t off = swz64((uint32_t)(row * 64 + chunk * 16));
                CP_ASYNC16((half ? uAlo[buf] : uAhi[buf]) + off, gp);
            } else {                        // B tiles: 2 x 256 chunks
                int sub   = idx - 1024;
                int half  = sub >> 8;
                int s2    = sub & 255;
                int row   = s2 >> 2;
                int chunk = s2 & 3;
                const __nv_bfloat16* gp =
                    (half ? Blo : Bhi) + (size_t)(n0 + row) * KTOT + kc + chunk * 8;
                uint32_t off = swz64((uint32_t)(row * 64 + chunk * 16));
                CP_ASYNC16((half ? uBlo[buf] : uBhi[buf]) + off, gp);
            }
        }
        CP_COMMIT();
    };

    issue_stage(0, 0);
#pragma unroll 1
    for (int ch = 0; ch < NCH; ch++) {
        const int buf = ch & 1;
        if (ch + 1 < NCH) { issue_stage(ch + 1, buf ^ 1); CP_WAIT(1); }
        else              { CP_WAIT(0); }
        __syncthreads();

        const int lrow = (lane & 7) + ((lane >> 3) & 1) * 8;   // 0..15
        const int lk   = ((lane >> 4) & 1) * 8;                 // 0 or 8
#pragma unroll
        for (int k16 = 0; k16 < 2; k16++) {
            const int kcol = k16 * 16 + lk;
            uint32_t ah[2][4], al[2][4], bh[4][2], bl[4][2];
#pragma unroll
            for (int i = 0; i < 2; i++) {
                uint32_t off = swz64((uint32_t)((wm + i*16 + lrow) * 64 + kcol * 2));
                ldsm4(ah[i], uAhi[buf] + off);
                ldsm4(al[i], uAlo[buf] + off);
            }
#pragma unroll
            for (int j2 = 0; j2 < 2; j2++) {
                uint32_t off = swz64((uint32_t)((wn + j2*16 + lrow) * 64 + kcol * 2));
                uint32_t r[4];
                ldsm4(r, uBhi[buf] + off);
                bh[j2*2][0] = r[0]; bh[j2*2+1][0] = r[1];
                bh[j2*2][1] = r[2]; bh[j2*2+1][1] = r[3];
                ldsm4(r, uBlo[buf] + off);
                bl[j2*2][0] = r[0]; bl[j2*2+1][0] = r[1];
                bl[j2*2][1] = r[2]; bl[j2*2+1][1] = r[3];
            }
#pragma unroll
            for (int i = 0; i < 2; i++)
#pragma unroll
                for (int j = 0; j < 4; j++) {
                    mma_bf16(acc[i][j], ah[i], bh[j]);   // hi*hi
                    mma_bf16(acc[i][j], ah[i], bl[j]);   // hi*lo
                    mma_bf16(acc[i][j], al[i], bh[j]);   // lo*hi
                }
        }
        __syncthreads();
    }

    // ---- epilogue -------------------------------------------------------
    const int g     = lane >> 2;        // 0..7
    const int cpair = (lane & 3) * 2;
#pragma unroll
    for (int i = 0; i < 2; i++) {
        const int rbase = m0 + wm + i*16 + g;
#pragma unroll
        for (int j = 0; j < 4; j++) {
            const int c0 = n0 + wn + j*8 + cpair;
            const float bz0 = bias[c0], bz1 = bias[c0+1];
#pragma unroll
            for (int half = 0; half < 2; half++) {
                const int r = rbase + half*8;
                const float v0r = acc[i][j][half*2+0] + bz0;
                const float v1r = acc[i][j][half*2+1] + bz1;
                if (MODE == 0) {
                    if (c0 < 256) {                 // h1: relu -> bf16 hi/lo
                        float v0 = fmaxf(v0r, 0.f), v1 = fmaxf(v1r, 0.f);
                        __nv_bfloat16 h0, l0, h1_, l1_;
                        bf16split(v0, h0, l0); bf16split(v1, h1_, l1_);
                        __nv_bfloat162 ph; ph.x = h0; ph.y = h1_;
                        __nv_bfloat162 pl; pl.x = l0; pl.y = l1_;
                        *(__nv_bfloat162*)&g_h1hi[(size_t)r*256 + c0] = ph;
                        *(__nv_bfloat162*)&g_h1lo[(size_t)r*256 + c0] = pl;
                    } else if (c0 < 512) {          // s: f32
                        float2 p; p.x = v0r; p.y = v1r;
                        *(float2*)&g_s[(size_t)r*256 + (c0-256)] = p;
                    } else {                        // m1: relu f32
                        float2 p; p.x = fmaxf(v0r, 0.f); p.y = fmaxf(v1r, 0.f);
                        *(float2*)&g_m1f[(size_t)r*128 + (c0-512)] = p;
                    }
                } else {                            // y2 = relu(.+b2) + s
                    float2 p;
                    p.x = fmaxf(v0r, 0.f) + g_s[(size_t)r*256 + c0];
                    p.y = fmaxf(v1r, 0.f) + g_s[(size_t)r*256 + c0 + 1];
                    *(float2*)&g_y2[(size_t)r*N2 + c0] = p;
                }
            }
        }
    }
}

// ---------------- GEMM2b (SIMT fp32): m2 = relu(m1 @ M2 + mb2) -----------
__global__ void gemm2b_kernel(const float* __restrict__ M2w,
                              const float* __restrict__ mb2)
{
    constexpr int BM=128, BN=64, BK=16, TM=8, TN=4, THREADS=256;
    __shared__ __align__(16) float As[BK*BM];
    __shared__ __align__(16) float Bs[BK*BN];
    const int tid  = threadIdx.x;
    const int row0 = blockIdx.x * BM;
    const int tm0  = (tid / (BN/TN)) * TM;
    const int tn0  = (tid % (BN/TN)) * TN;
    float4 pa[2], pb[1];

    auto loadg = [&](int k0) {
#pragma unroll
        for (int i = 0; i < 2; i++) {
            int idx = tid + i*THREADS; int m = idx / 4; int kv = idx % 4;
            pa[i] = *(const float4*)(g_m1f + (size_t)(row0+m)*128 + k0 + kv*4);
        }
        { int kr = tid / 16; int nv = tid % 16;
          pb[0] = *(const float4*)(M2w + (size_t)(k0 + kr)*64 + nv*4); }
    };
    auto stage = [&]() {
#pragma unroll
        for (int i = 0; i < 2; i++) {
            int idx = tid + i*THREADS; int m = idx / 4; int kv = idx % 4;
            As[(kv*4+0)*BM+m]=pa[i].x; As[(kv*4+1)*BM+m]=pa[i].y;
            As[(kv*4+2)*BM+m]=pa[i].z; As[(kv*4+3)*BM+m]=pa[i].w;
        }
        { int kr = tid / 16; int nv = tid % 16;
          *(float4*)&Bs[kr*BN + nv*4] = pb[0]; }
    };

    float acc[TM][TN];
#pragma unroll
    for (int i=0;i<TM;i++)
#pragma unroll
        for (int j=0;j<TN;j++) acc[i][j]=0.f;

    loadg(0);
#pragma unroll 1
    for (int t = 0; t < 128/BK; t++) {
        __syncthreads(); stage(); __syncthreads();
        if (t+1 < 128/BK) loadg((t+1)*BK);
#pragma unroll
        for (int kk = 0; kk < BK; kk++) {
            float af[TM], bf[TN];
#pragma unroll
            for (int i=0;i<TM/4;i++) *(float4*)&af[i*4] = *(const float4*)&As[kk*BM+tm0+i*4];
            *(float4*)&bf[0] = *(const float4*)&Bs[kk*BN+tn0];
#pragma unroll
            for (int i=0;i<TM;i++)
#pragma unroll
                for (int j=0;j<TN;j++) acc[i][j] = fmaf(af[i], bf[j], acc[i][j]);
        }
    }
#pragma unroll
    for (int i=0;i<TM;i++) {
        int r = row0 + tm0 + i;
#pragma unroll
        for (int j=0;j<TN;j++) {
            int n = tn0 + j;
            g_y2[(size_t)r*N2 + 256 + n] = fmaxf(acc[i][j] + mb2[n], 0.f);
        }
    }
}

// ---------------- heads --------------------------------------------------
__global__ void head_kernel(const float* __restrict__ Wo,
                            const float* __restrict__ bo,
                            const float* __restrict__ M3,
                            const float* __restrict__ mb3,
                            float* __restrict__ out)
{
    const int row  = blockIdx.x * 8 + (threadIdx.x >> 5);
    const int lane = threadIdx.x & 31;
    const float* y = g_y2 + (size_t)row * N2;

    float a0=0.f, a1=0.f, a2=0.f, am=0.f;
#pragma unroll
    for (int c = lane; c < 256; c += 32) {
        float h = y[c];
        a0 = fmaf(h, Wo[c*3+0], a0);
        a1 = fmaf(h, Wo[c*3+1], a1);
        a2 = fmaf(h, Wo[c*3+2], a2);
    }
#pragma unroll
    for (int c = lane; c < 64; c += 32)
        am = fmaf(y[256+c], M3[c], am);
#pragma unroll
    for (int o = 16; o > 0; o >>= 1) {
        a0 += __shfl_xor_sync(0xffffffffu, a0, o);
        a1 += __shfl_xor_sync(0xffffffffu, a1, o);
        a2 += __shfl_xor_sync(0xffffffffu, a2, o);
        am += __shfl_xor_sync(0xffffffffu, am, o);
    }
    if (lane == 0) {
        out[row*3+0] = (a0 + bo[0]) * 0.3f;
        out[row*3+1] = (a1 + bo[1]) * 0.3f;
        out[row*3+2] = (a2 + bo[2]) * 0.3f;
        float x = am + mb3[0];
        out[ROWS*3 + row] = 1.f / (1.f + expf(-x));
    }
}

// --------------------------------- launch --------------------------------
extern "C" void kernel_launch(void* const* d_in, const int* in_sizes, int n_in,
                              void* d_out, int out_size)
{
    const float* tmpl  = (const float*)d_in[0];
    const float* surf  = (const float*)d_in[1];
    const float* gfeat = (const float*)d_in[2];
    const float* pfeat = (const float*)d_in[3];
    const float* W1 = (const float*)d_in[4];
    const float* b1 = (const float*)d_in[5];
    const float* W2 = (const float*)d_in[6];
    const float* b2 = (const float*)d_in[7];
    const float* Ws = (const float*)d_in[8];
    const float* bs = (const float*)d_in[9];
    const float* Wo = (const float*)d_in[10];
    const float* bo = (const float*)d_in[11];
    const float* M1 = (const float*)d_in[12];
    const float* mb1 = (const float*)d_in[13];
    const float* M2 = (const float*)d_in[14];
    const float* mb2 = (const float*)d_in[15];
    const float* M3 = (const float*)d_in[16];
    const float* mb3 = (const float*)d_in[17];
    float* out = (float*)d_out;

    knn_kernel<<<dim3(TT/128, BB), 128>>>(tmpl, surf);
    prepack_kernel<<<(N1*KPAD1 + 255)/256, 256>>>(W1, Ws, M1, b1, bs, mb1, W2);
    build_ni_kernel<<<ROWS, 256>>>(tmpl, gfeat, pfeat);

    // GEMM1: [32768 x 832] @ [832 x 640] (compensated bf16 mma.sync)
    mma_gemm<0><<<dim3(N1/64, ROWS/128), 256>>>(nullptr);
    // GEMM2a: h2 = relu(h1@W2+b2)+s  [32768 x 256] K=256
    mma_gemm<1><<<dim3(256/64, ROWS/128), 256>>>(b2);
    // GEMM2b: m2 = relu(m1@M2+mb2)   [32768 x 64]  K=128 (SIMT)
    gemm2b_kernel<<<ROWS/128, 256>>>(M2, mb2);

    head_kernel<<<ROWS/8, 256>>>(Wo, bo, M3, mb3, out);
}

// round 6
// speedup vs baseline: 1.9449x; 1.0055x over previous
#include <cuda_runtime.h>
#include <cuda_bf16.h>
#include <math.h>
#include <float.h>
#include <stdint.h>

// Problem constants
#define BB 4
#define TT 8192
#define SS 4096
#define DD 256
#define GG 512
#define KK 8
#define ROWS (BB*TT)        // 32768
#define NIP 771
#define KPAD1 832           // 13 * 64
#define N1 640              // 256 (W1) + 256 (Ws) + 128 (M1)
#define MATOFF (ROWS*3)     // offset of mat in out

// ---------------- scratch (device globals; no allocation) ----------------
__device__ __align__(128) int   g_idx[ROWS * KK];
__device__ __align__(128) float g_d2 [ROWS * KK];
__device__ __align__(128) __nv_bfloat16 g_ni_hi[(size_t)ROWS * KPAD1];
__device__ __align__(128) __nv_bfloat16 g_ni_lo[(size_t)ROWS * KPAD1];
__device__ __align__(128) __nv_bfloat16 g_w1t_hi[N1 * KPAD1];
__device__ __align__(128) __nv_bfloat16 g_w1t_lo[N1 * KPAD1];
__device__ __align__(128) __nv_bfloat16 g_w2t_hi[256 * 256];
__device__ __align__(128) __nv_bfloat16 g_w2t_lo[256 * 256];
__device__ __align__(128) float g_bias1[N1];
__device__ __align__(128) __nv_bfloat16 g_h1hi[(size_t)ROWS * 256];
__device__ __align__(128) __nv_bfloat16 g_h1lo[(size_t)ROWS * 256];
__device__ __align__(128) float g_s  [(size_t)ROWS * 256];
__device__ __align__(128) float g_m1f[(size_t)ROWS * 128];

// =================== helpers =============================================
__device__ __forceinline__ uint32_t smem_to_u32(const void* p) {
    uint32_t a;
    asm("{ .reg .u64 t; cvta.to.shared.u64 t, %1; cvt.u32.u64 %0, t; }" : "=r"(a) : "l"(p));
    return a;
}
__device__ __forceinline__ void ldsm4(uint32_t* r, uint32_t addr) {
    asm volatile("ldmatrix.sync.aligned.m8n8.x4.shared.b16 {%0,%1,%2,%3}, [%4];"
        : "=r"(r[0]), "=r"(r[1]), "=r"(r[2]), "=r"(r[3]) : "r"(addr));
}
__device__ __forceinline__ void mma_bf16(float* c, const uint32_t* a, const uint32_t* b) {
    asm volatile("mma.sync.aligned.m16n8k16.row.col.f32.bf16.bf16.f32 "
        "{%0,%1,%2,%3}, {%4,%5,%6,%7}, {%8,%9}, {%0,%1,%2,%3};"
        : "+f"(c[0]), "+f"(c[1]), "+f"(c[2]), "+f"(c[3])
        : "r"(a[0]), "r"(a[1]), "r"(a[2]), "r"(a[3]), "r"(b[0]), "r"(b[1]));
}
#define CP_ASYNC16(dst, src) \
    asm volatile("cp.async.cg.shared.global [%0], [%1], 16;" :: "r"(dst), "l"(src))
#define CP_COMMIT()  asm volatile("cp.async.commit_group;" ::: "memory")
#define CP_WAIT(n)   asm volatile("cp.async.wait_group %0;" :: "n"(n) : "memory")

// swizzle for tiles with 64-byte rows (32 bf16)
__device__ __forceinline__ uint32_t swz64(uint32_t off) {
    return off ^ (((off >> 7) & 3u) << 4);
}
__device__ __forceinline__ void bf16split(float v, __nv_bfloat16& h, __nv_bfloat16& l) {
    h = __float2bfloat16(v);
    l = __float2bfloat16(v - __bfloat162float(h));
}

// ---------------- KNN: top-8 nearest surf points per template point ------
__global__ void knn_kernel(const float* __restrict__ tmpl,
                           const float* __restrict__ surf)
{
    __shared__ float4 ss[2048];
    const int b   = blockIdx.y;
    const int t   = blockIdx.x * 128 + threadIdx.x;
    const int row = b * TT + t;

    const float tx = tmpl[row*3+0];
    const float ty = tmpl[row*3+1];
    const float tz = tmpl[row*3+2];

    float bd[KK]; int bi[KK];
#pragma unroll
    for (int q = 0; q < KK; q++) { bd[q] = FLT_MAX; bi[q] = 0; }
    const float* sb = surf + (size_t)b * SS * 3;

    for (int tile = 0; tile < 2; tile++) {
        __syncthreads();
        for (int i = threadIdx.x; i < 2048; i += 128) {
            int sp = tile * 2048 + i;
            ss[i] = make_float4(sb[sp*3+0], sb[sp*3+1], sb[sp*3+2], 0.f);
        }
        __syncthreads();
#pragma unroll 4
        for (int j = 0; j < 2048; j++) {
            float4 p = ss[j];
            float dx = tx - p.x, dy = ty - p.y, dz = tz - p.z;
            float d2 = fmaf(dx, dx, fmaf(dy, dy, dz*dz));
            if (d2 < bd[KK-1]) {
                float v = d2; int vi = tile * 2048 + j;
#pragma unroll
                for (int q = 0; q < KK; q++) {
                    if (v < bd[q]) {
                        float tv = bd[q]; int ti = bi[q];
                        bd[q] = v; bi[q] = vi; v = tv; vi = ti;
                    }
                }
            }
        }
    }
#pragma unroll
    for (int q = 0; q < KK; q++) {
        g_d2 [row*KK+q] = bd[q];
        g_idx[row*KK+q] = bi[q];
    }
}

// ---------------- prepack + out disp init --------------------------------
__global__ void prepack_kernel(const float* __restrict__ W1,
                               const float* __restrict__ Ws,
                               const float* __restrict__ M1,
                               const float* __restrict__ b1,
                               const float* __restrict__ bs,
                               const float* __restrict__ mb1,
                               const float* __restrict__ W2,
                               const float* __restrict__ bo,
                               float* __restrict__ out)
{
    int idx = blockIdx.x * 256 + threadIdx.x;
    if (idx < N1 * KPAD1) {
        int n = idx / KPAD1, k = idx % KPAD1;
        float v = 0.f;
        if (k < NIP) {
            if (n < 256)       v = W1[k*256 + n];
            else if (n < 512)  v = Ws[k*256 + (n-256)];
            else               v = M1[k*128 + (n-512)];
        }
        __nv_bfloat16 h, l; bf16split(v, h, l);
        g_w1t_hi[idx] = h; g_w1t_lo[idx] = l;
    }
    if (idx < 256 * 256) {
        int n = idx / 256, k = idx % 256;
        __nv_bfloat16 h, l; bf16split(W2[k*256 + n], h, l);
        g_w2t_hi[idx] = h; g_w2t_lo[idx] = l;
    }
    if (idx < N1) {
        float bv;
        if (idx < 256)       bv = b1[idx];
        else if (idx < 512)  bv = bs[idx-256];
        else                 bv = mb1[idx-512];
        g_bias1[idx] = bv;
    }
    if (idx < MATOFF)                      // init disp = 0.3 * bo
        out[idx] = bo[idx % 3] * 0.3f;
}

// ---------------- build ni -> bf16 hi/lo with packed stores --------------
__global__ void build_ni_kernel(const float* __restrict__ tmpl,
                                const float* __restrict__ gfeat,
                                const float* __restrict__ pfeat)
{
    __shared__ float srow[KPAD1];
    const int row = blockIdx.x;
    const int tid = threadIdx.x;
    const int b   = row >> 13;

    float w[KK]; int id[KK]; float wsum = 0.f;
#pragma unroll
    for (int k = 0; k < KK; k++) {
        id[k] = g_idx[row*KK+k];
        float d = sqrtf(g_d2[row*KK+k]);
        w[k] = 1.f / (d + 1e-8f);
        wsum += w[k];
    }
    float inv = 1.f / wsum;
#pragma unroll
    for (int k = 0; k < KK; k++) w[k] *= inv;

    const float* pfb = pfeat + (size_t)b * SS * DD;
    float acc = 0.f;
#pragma unroll
    for (int k = 0; k < KK; k++)
        acc = fmaf(w[k], pfb[(size_t)id[k]*DD + tid], acc);

    srow[3 + tid]   = acc;
    srow[259 + tid] = gfeat[b*GG + tid];
    srow[515 + tid] = gfeat[b*GG + 256 + tid];
    if (tid < 3)            srow[tid] = tmpl[row*3 + tid];
    if (tid < KPAD1 - NIP)  srow[NIP + tid] = 0.f;
    __syncthreads();

    if (tid < 208) {                      // 208 * 4 = 832 elems
        __nv_bfloat16 hv[4], lv[4];
#pragma unroll
        for (int q = 0; q < 4; q++)
            bf16split(srow[tid*4 + q], hv[q], lv[q]);
        *(uint2*)&g_ni_hi[(size_t)row * KPAD1 + tid*4] = *(uint2*)hv;
        *(uint2*)&g_ni_lo[(size_t)row * KPAD1 + tid*4] = *(uint2*)lv;
    }
}

// =============== mma.sync compensated bf16 GEMM (128x64, BK=32) ==========
// MODE 0: GEMM1   A=ni (K=832), B=w1t -> h1(bf16 hi/lo)/s(f32)/m1(f32)
// MODE 1: GEMM2a  A=h1 (K=256), B=w2t -> fused disp head (atomicAdd to out)
#define A_TILE_B 8192        // 128 rows x 64 bytes
#define B_TILE_B 4096        // 64 rows x 64 bytes

template<int MODE>
__global__ void __launch_bounds__(256, 3) mma_gemm(const float* __restrict__ biasext,
                                                   const float* __restrict__ Wo,
                                                   float* __restrict__ out)
{
    constexpr int KTOT = (MODE == 0) ? KPAD1 : 256;
    constexpr int NCH  = KTOT / 32;

    __shared__ __align__(128) __nv_bfloat16 sAhi[2][A_TILE_B/2];
    __shared__ __align__(128) __nv_bfloat16 sAlo[2][A_TILE_B/2];
    __shared__ __align__(128) __nv_bfloat16 sBhi[2][B_TILE_B/2];
    __shared__ __align__(128) __nv_bfloat16 sBlo[2][B_TILE_B/2];

    const int tid  = threadIdx.x;
    const int wid  = tid >> 5;
    const int lane = tid & 31;
    const int m0 = blockIdx.y * 128;
    const int n0 = blockIdx.x * 64;

    const __nv_bfloat16 *Ahi, *Alo, *Bhi, *Blo;
    const float* bias;
    if (MODE == 0) { Ahi = g_ni_hi; Alo = g_ni_lo; Bhi = g_w1t_hi; Blo = g_w1t_lo; bias = g_bias1; }
    else           { Ahi = g_h1hi;  Alo = g_h1lo;  Bhi = g_w2t_hi; Blo = g_w2t_lo; bias = biasext; }

    const uint32_t uAhi[2] = { smem_to_u32(sAhi[0]), smem_to_u32(sAhi[1]) };
    const uint32_t uAlo[2] = { smem_to_u32(sAlo[0]), smem_to_u32(sAlo[1]) };
    const uint32_t uBhi[2] = { smem_to_u32(sBhi[0]), smem_to_u32(sBhi[1]) };
    const uint32_t uBlo[2] = { smem_to_u32(sBlo[0]), smem_to_u32(sBlo[1]) };

    const int wm = (wid & 3) * 32;       // warp m-offset (4 row-warps)
    const int wn = (wid >> 2) * 32;      // warp n-offset (2 col-warps)

    float acc[2][4][4];
#pragma unroll
    for (int i = 0; i < 2; i++)
#pragma unroll
        for (int j = 0; j < 4; j++)
#pragma unroll
            for (int q = 0; q < 4; q++) acc[i][j][q] = 0.f;

    auto issue_stage = [&](int ch, int buf) {
        const int kc = ch * 32;
#pragma unroll
        for (int t = 0; t < 6; t++) {
            int idx = tid + t * 256;
            if (idx < 1024) {               // A tiles: 2 x 512 chunks
                int half  = idx >> 9;
                int sub   = idx & 511;
                int row   = sub >> 2;
                int chunk = sub & 3;
                const __nv_bfloat16* gp =
                    (half ? Alo : Ahi) + (size_t)(m0 + row) * KTOT + kc + chunk * 8;
                uint32_t off = swz64((uint32_t)(row * 64 + chunk * 16));
                CP_ASYNC16((half ? uAlo[buf] : uAhi[buf]) + off, gp);
            } else {                        // B tiles: 2 x 256 chunks
                int sub   = idx - 1024;
                int half  = sub >> 8;
                int s2    = sub & 255;
                int row   = s2 >> 2;
                int chunk = s2 & 3;
                const __nv_bfloat16* gp =
                    (half ? Blo : Bhi) + (size_t)(n0 + row) * KTOT + kc + chunk * 8;
                uint32_t off = swz64((uint32_t)(row * 64 + chunk * 16));
                CP_ASYNC16((half ? uBlo[buf] : uBhi[buf]) + off, gp);
            }
        }
        CP_COMMIT();
    };

    issue_stage(0, 0);
#pragma unroll 1
    for (int ch = 0; ch < NCH; ch++) {
        const int buf = ch & 1;
        if (ch + 1 < NCH) { issue_stage(ch + 1, buf ^ 1); CP_WAIT(1); }
        else              { CP_WAIT(0); }
        __syncthreads();

        const int lrow = (lane & 7) + ((lane >> 3) & 1) * 8;   // 0..15
        const int lk   = ((lane >> 4) & 1) * 8;                 // 0 or 8
#pragma unroll
        for (int k16 = 0; k16 < 2; k16++) {
            const int kcol = k16 * 16 + lk;
            uint32_t bh[4][2], bl[4][2];
#pragma unroll
            for (int j2 = 0; j2 < 2; j2++) {
                uint32_t off = swz64((uint32_t)((wn + j2*16 + lrow) * 64 + kcol * 2));
                uint32_t r[4];
                ldsm4(r, uBhi[buf] + off);
                bh[j2*2][0] = r[0]; bh[j2*2+1][0] = r[1];
                bh[j2*2][1] = r[2]; bh[j2*2+1][1] = r[3];
                ldsm4(r, uBlo[buf] + off);
                bl[j2*2][0] = r[0]; bl[j2*2+1][0] = r[1];
                bl[j2*2][1] = r[2]; bl[j2*2+1][1] = r[3];
            }
#pragma unroll
            for (int i = 0; i < 2; i++) {
                uint32_t af[4];
                uint32_t off = swz64((uint32_t)((wm + i*16 + lrow) * 64 + kcol * 2));
                ldsm4(af, uAhi[buf] + off);
#pragma unroll
                for (int j = 0; j < 4; j++) {
                    mma_bf16(acc[i][j], af, bh[j]);   // hi*hi
                    mma_bf16(acc[i][j], af, bl[j]);   // hi*lo
                }
                ldsm4(af, uAlo[buf] + off);
#pragma unroll
                for (int j = 0; j < 4; j++)
                    mma_bf16(acc[i][j], af, bh[j]);   // lo*hi
            }
        }
        __syncthreads();
    }

    // ---- epilogue -------------------------------------------------------
    const int g     = lane >> 2;        // 0..7
    const int cpair = (lane & 3) * 2;
#pragma unroll
    for (int i = 0; i < 2; i++) {
#pragma unroll
        for (int half = 0; half < 2; half++) {
            const int r = m0 + wm + i*16 + g + half*8;
            if (MODE == 0) {
#pragma unroll
                for (int j = 0; j < 4; j++) {
                    const int c0 = n0 + wn + j*8 + cpair;
                    const float v0r = acc[i][j][half*2+0] + bias[c0];
                    const float v1r = acc[i][j][half*2+1] + bias[c0+1];
                    if (c0 < 256) {                 // h1: relu -> bf16 hi/lo
                        float v0 = fmaxf(v0r, 0.f), v1 = fmaxf(v1r, 0.f);
                        __nv_bfloat16 h0, l0, h1_, l1_;
                        bf16split(v0, h0, l0); bf16split(v1, h1_, l1_);
                        __nv_bfloat162 ph; ph.x = h0; ph.y = h1_;
                        __nv_bfloat162 pl; pl.x = l0; pl.y = l1_;
                        *(__nv_bfloat162*)&g_h1hi[(size_t)r*256 + c0] = ph;
                        *(__nv_bfloat162*)&g_h1lo[(size_t)r*256 + c0] = pl;
                    } else if (c0 < 512) {          // s: f32
                        float2 p; p.x = v0r; p.y = v1r;
                        *(float2*)&g_s[(size_t)r*256 + (c0-256)] = p;
                    } else {                        // m1: relu f32
                        float2 p; p.x = fmaxf(v0r, 0.f); p.y = fmaxf(v1r, 0.f);
                        *(float2*)&g_m1f[(size_t)r*128 + (c0-512)] = p;
                    }
                }
            } else {
                // h2 = relu(acc+b2)+s, then partial disp = h2 . Wo
                float d0 = 0.f, d1 = 0.f, d2 = 0.f;
#pragma unroll
                for (int j = 0; j < 4; j++) {
                    const int c0 = n0 + wn + j*8 + cpair;
                    float v0 = fmaxf(acc[i][j][half*2+0] + bias[c0],   0.f)
                               + g_s[(size_t)r*256 + c0];
                    float v1 = fmaxf(acc[i][j][half*2+1] + bias[c0+1], 0.f)
                               + g_s[(size_t)r*256 + c0 + 1];
                    d0 = fmaf(v0, Wo[c0*3+0], fmaf(v1, Wo[(c0+1)*3+0], d0));
                    d1 = fmaf(v0, Wo[c0*3+1], fmaf(v1, Wo[(c0+1)*3+1], d1));
                    d2 = fmaf(v0, Wo[c0*3+2], fmaf(v1, Wo[(c0+1)*3+2], d2));
                }
#pragma unroll
                for (int o = 1; o <= 2; o <<= 1) {
                    d0 += __shfl_xor_sync(0xffffffffu, d0, o);
                    d1 += __shfl_xor_sync(0xffffffffu, d1, o);
                    d2 += __shfl_xor_sync(0xffffffffu, d2, o);
                }
                if ((lane & 3) == 0) {
                    atomicAdd(&out[r*3+0], 0.3f * d0);
                    atomicAdd(&out[r*3+1], 0.3f * d1);
                    atomicAdd(&out[r*3+2], 0.3f * d2);
                }
            }
        }
    }
}

// ---------------- GEMM2b + mat head: mat = sigmoid(relu(m1@M2+mb2)@M3+mb3)
__global__ void gemm2b_kernel(const float* __restrict__ M2w,
                              const float* __restrict__ mb2,
                              const float* __restrict__ M3,
                              const float* __restrict__ mb3,
                              float* __restrict__ out)
{
    constexpr int BM=128, BN=64, BK=16, TM=8, TN=4, THREADS=256;
    __shared__ __align__(16) float As[BK*BM];
    __shared__ __align__(16) float Bs[BK*BN];
    const int tid  = threadIdx.x;
    const int row0 = blockIdx.x * BM;
    const int tm0  = (tid / (BN/TN)) * TM;
    const int tn0  = (tid % (BN/TN)) * TN;
    float4 pa[2], pb[1];

    auto loadg = [&](int k0) {
#pragma unroll
        for (int i = 0; i < 2; i++) {
            int idx = tid + i*THREADS; int m = idx / 4; int kv = idx % 4;
            pa[i] = *(const float4*)(g_m1f + (size_t)(row0+m)*128 + k0 + kv*4);
        }
        { int kr = tid / 16; int nv = tid % 16;
          pb[0] = *(const float4*)(M2w + (size_t)(k0 + kr)*64 + nv*4); }
    };
    auto stage = [&]() {
#pragma unroll
        for (int i = 0; i < 2; i++) {
            int idx = tid + i*THREADS; int m = idx / 4; int kv = idx % 4;
            As[(kv*4+0)*BM+m]=pa[i].x; As[(kv*4+1)*BM+m]=pa[i].y;
            As[(kv*4+2)*BM+m]=pa[i].z; As[(kv*4+3)*BM+m]=pa[i].w;
        }
        { int kr = tid / 16; int nv = tid % 16;
          *(float4*)&Bs[kr*BN + nv*4] = pb[0]; }
    };

    float acc[TM][TN];
#pragma unroll
    for (int i=0;i<TM;i++)
#pragma unroll
        for (int j=0;j<TN;j++) acc[i][j]=0.f;

    loadg(0);
#pragma unroll 1
    for (int t = 0; t < 128/BK; t++) {
        __syncthreads(); stage(); __syncthreads();
        if (t+1 < 128/BK) loadg((t+1)*BK);
#pragma unroll
        for (int kk = 0; kk < BK; kk++) {
            float af[TM], bf[TN];
#pragma unroll
            for (int i=0;i<TM/4;i++) *(float4*)&af[i*4] = *(const float4*)&As[kk*BM+tm0+i*4];
            *(float4*)&bf[0] = *(const float4*)&Bs[kk*BN+tn0];
#pragma unroll
            for (int i=0;i<TM;i++)
#pragma unroll
                for (int j=0;j<TN;j++) acc[i][j] = fmaf(af[i], bf[j], acc[i][j]);
        }
    }

    // mat head: row's 64 cols live in the 16 threads sharing tid/16
    float mv[TM];
#pragma unroll
    for (int i=0;i<TM;i++) {
        float m = 0.f;
#pragma unroll
        for (int j=0;j<TN;j++) {
            int n = tn0 + j;
            m = fmaf(fmaxf(acc[i][j] + mb2[n], 0.f), M3[n], m);
        }
        mv[i] = m;
    }
#pragma unroll
    for (int o = 1; o <= 8; o <<= 1)
#pragma unroll
        for (int i=0;i<TM;i++)
            mv[i] += __shfl_xor_sync(0xffffffffu, mv[i], o);
    if ((tid & 15) == 0) {
        const float b3 = mb3[0];
#pragma unroll
        for (int i=0;i<TM;i++) {
            float x = mv[i] + b3;
            out[MATOFF + row0 + tm0 + i] = 1.f / (1.f + expf(-x));
        }
    }
}

// --------------------------------- launch --------------------------------
extern "C" void kernel_launch(void* const* d_in, const int* in_sizes, int n_in,
                              void* d_out, int out_size)
{
    const float* tmpl  = (const float*)d_in[0];
    const float* surf  = (const float*)d_in[1];
    const float* gfeat = (const float*)d_in[2];
    const float* pfeat = (const float*)d_in[3];
    const float* W1 = (const float*)d_in[4];
    const float* b1 = (const float*)d_in[5];
    const float* W2 = (const float*)d_in[6];
    const float* b2 = (const float*)d_in[7];
    const float* Ws = (const float*)d_in[8];
    const float* bs = (const float*)d_in[9];
    const float* Wo = (const float*)d_in[10];
    const float* bo = (const float*)d_in[11];
    const float* M1 = (const float*)d_in[12];
    const float* mb1 = (const float*)d_in[13];
    const float* M2 = (const float*)d_in[14];
    const float* mb2 = (const float*)d_in[15];
    const float* M3 = (const float*)d_in[16];
    const float* mb3 = (const float*)d_in[17];
    float* out = (float*)d_out;

    knn_kernel<<<dim3(TT/128, BB), 128>>>(tmpl, surf);
    prepack_kernel<<<(N1*KPAD1 + 255)/256, 256>>>(W1, Ws, M1, b1, bs, mb1, W2, bo, out);
    build_ni_kernel<<<ROWS, 256>>>(tmpl, gfeat, pfeat);

    // GEMM1: [32768 x 832] @ [832 x 640] (compensated bf16 mma.sync)
    mma_gemm<0><<<dim3(N1/64, ROWS/128), 256>>>(nullptr, nullptr, nullptr);
    // GEMM2a + disp head: h2 = relu(h1@W2+b2)+s ; atomicAdd 0.3*(h2.Wo)
    mma_gemm<1><<<dim3(256/64, ROWS/128), 256>>>(b2, Wo, out);
    // GEMM2b + mat head
    gemm2b_kernel<<<ROWS/128, 256>>>(M2, mb2, M3, mb3, out);
}

// round 7
// speedup vs baseline: 2.6356x; 1.3551x over previous
#include <cuda_runtime.h>
#include <cuda_bf16.h>
#include <math.h>
#include <float.h>
#include <stdint.h>

// Problem constants
#define BB 4
#define TT 8192
#define SS 4096
#define DD 256
#define GG 512
#define KK 8
#define ROWS (BB*TT)        // 32768
#define NREAL 259           // template(3) + local(256); global folded into bias
#define KPAD1 288           // 9 * 32
#define N1 640              // 256 (W1) + 256 (Ws) + 128 (M1)
#define MATOFF (ROWS*3)     // offset of mat in out

// ---------------- scratch (device globals; no allocation) ----------------
__device__ __align__(128) int   g_idx[ROWS * KK];
__device__ __align__(128) float g_d2 [ROWS * KK];
__device__ __align__(128) __nv_bfloat16 g_ni_hi[(size_t)ROWS * KPAD1];
__device__ __align__(128) __nv_bfloat16 g_ni_lo[(size_t)ROWS * KPAD1];
__device__ __align__(128) __nv_bfloat16 g_w1t_hi[N1 * KPAD1];
__device__ __align__(128) __nv_bfloat16 g_w1t_lo[N1 * KPAD1];
__device__ __align__(128) __nv_bfloat16 g_w2t_hi[256 * 256];
__device__ __align__(128) __nv_bfloat16 g_w2t_lo[256 * 256];
__device__ __align__(128) float g_bias1[N1];
__device__ __align__(128) float g_bias_eff[BB * N1];   // bias1 + gfeat@W_global
__device__ __align__(128) __nv_bfloat16 g_h1hi[(size_t)ROWS * 256];
__device__ __align__(128) __nv_bfloat16 g_h1lo[(size_t)ROWS * 256];
__device__ __align__(128) float g_s  [(size_t)ROWS * 256];
__device__ __align__(128) float g_m1f[(size_t)ROWS * 128];

// =================== helpers =============================================
__device__ __forceinline__ uint32_t smem_to_u32(const void* p) {
    uint32_t a;
    asm("{ .reg .u64 t; cvta.to.shared.u64 t, %1; cvt.u32.u64 %0, t; }" : "=r"(a) : "l"(p));
    return a;
}
__device__ __forceinline__ void ldsm4(uint32_t* r, uint32_t addr) {
    asm volatile("ldmatrix.sync.aligned.m8n8.x4.shared.b16 {%0,%1,%2,%3}, [%4];"
        : "=r"(r[0]), "=r"(r[1]), "=r"(r[2]), "=r"(r[3]) : "r"(addr));
}
__device__ __forceinline__ void mma_bf16(float* c, const uint32_t* a, const uint32_t* b) {
    asm volatile("mma.sync.aligned.m16n8k16.row.col.f32.bf16.bf16.f32 "
        "{%0,%1,%2,%3}, {%4,%5,%6,%7}, {%8,%9}, {%0,%1,%2,%3};"
        : "+f"(c[0]), "+f"(c[1]), "+f"(c[2]), "+f"(c[3])
        : "r"(a[0]), "r"(a[1]), "r"(a[2]), "r"(a[3]), "r"(b[0]), "r"(b[1]));
}
#define CP_ASYNC16(dst, src) \
    asm volatile("cp.async.cg.shared.global [%0], [%1], 16;" :: "r"(dst), "l"(src))
#define CP_COMMIT()  asm volatile("cp.async.commit_group;" ::: "memory")
#define CP_WAIT(n)   asm volatile("cp.async.wait_group %0;" :: "n"(n) : "memory")

// swizzle for tiles with 64-byte rows (32 bf16)
__device__ __forceinline__ uint32_t swz64(uint32_t off) {
    return off ^ (((off >> 7) & 3u) << 4);
}
__device__ __forceinline__ void bf16split(float v, __nv_bfloat16& h, __nv_bfloat16& l) {
    h = __float2bfloat16(v);
    l = __float2bfloat16(v - __bfloat162float(h));
}

// ---------------- KNN: top-8 nearest surf points per template point ------
__global__ void knn_kernel(const float* __restrict__ tmpl,
                           const float* __restrict__ surf)
{
    __shared__ float4 ss[2048];
    const int b   = blockIdx.y;
    const int t   = blockIdx.x * 128 + threadIdx.x;
    const int row = b * TT + t;

    const float tx = tmpl[row*3+0];
    const float ty = tmpl[row*3+1];
    const float tz = tmpl[row*3+2];

    float bd[KK]; int bi[KK];
#pragma unroll
    for (int q = 0; q < KK; q++) { bd[q] = FLT_MAX; bi[q] = 0; }
    const float* sb = surf + (size_t)b * SS * 3;

    for (int tile = 0; tile < 2; tile++) {
        __syncthreads();
        for (int i = threadIdx.x; i < 2048; i += 128) {
            int sp = tile * 2048 + i;
            ss[i] = make_float4(sb[sp*3+0], sb[sp*3+1], sb[sp*3+2], 0.f);
        }
        __syncthreads();
#pragma unroll 4
        for (int j = 0; j < 2048; j++) {
            float4 p = ss[j];
            float dx = tx - p.x, dy = ty - p.y, dz = tz - p.z;
            float d2 = fmaf(dx, dx, fmaf(dy, dy, dz*dz));
            if (d2 < bd[KK-1]) {
                float v = d2; int vi = tile * 2048 + j;
#pragma unroll
                for (int q = 0; q < KK; q++) {
                    if (v < bd[q]) {
                        float tv = bd[q]; int ti = bi[q];
                        bd[q] = v; bi[q] = vi; v = tv; vi = ti;
                    }
                }
            }
        }
    }
#pragma unroll
    for (int q = 0; q < KK; q++) {
        g_d2 [row*KK+q] = bd[q];
        g_idx[row*KK+q] = bi[q];
    }
}

// ---------------- prepack + out disp init --------------------------------
__global__ void prepack_kernel(const float* __restrict__ W1,
                               const float* __restrict__ Ws,
                               const float* __restrict__ M1,
                               const float* __restrict__ b1,
                               const float* __restrict__ bs,
                               const float* __restrict__ mb1,
                               const float* __restrict__ W2,
                               const float* __restrict__ bo,
                               float* __restrict__ out)
{
    int idx = blockIdx.x * 256 + threadIdx.x;
    if (idx < N1 * KPAD1) {
        int n = idx / KPAD1, k = idx % KPAD1;
        float v = 0.f;
        if (k < NREAL) {                   // orig input index == k for k<259
            if (n < 256)       v = W1[k*256 + n];
            else if (n < 512)  v = Ws[k*256 + (n-256)];
            else               v = M1[k*128 + (n-512)];
        }
        __nv_bfloat16 h, l; bf16split(v, h, l);
        g_w1t_hi[idx] = h; g_w1t_lo[idx] = l;
    }
    if (idx < 256 * 256) {
        int n = idx / 256, k = idx % 256;
        __nv_bfloat16 h, l; bf16split(W2[k*256 + n], h, l);
        g_w2t_hi[idx] = h; g_w2t_lo[idx] = l;
    }
    if (idx < N1) {
        float bv;
        if (idx < 256)       bv = b1[idx];
        else if (idx < 512)  bv = bs[idx-256];
        else                 bv = mb1[idx-512];
        g_bias1[idx] = bv;
    }
    if (idx < MATOFF)                      // init disp = 0.3 * bo
        out[idx] = bo[idx % 3] * 0.3f;
}

// ---------------- fold global_feat into bias (fp32 exact) ----------------
// bias_eff[b][n] = bias1[n] + sum_j gfeat[b,j] * W(259+j, n)
__global__ void gvec_kernel(const float* __restrict__ gfeat,
                            const float* __restrict__ W1,
                            const float* __restrict__ Ws,
                            const float* __restrict__ M1)
{
    const int b = blockIdx.x;
    const int n = blockIdx.y * 128 + threadIdx.x;
    const float* gf = gfeat + b * GG;
    float acc = 0.f;
    if (n < 256) {
        const float* w = W1 + 259*256 + n;
#pragma unroll 8
        for (int j = 0; j < GG; j++) acc = fmaf(gf[j], w[j*256], acc);
    } else if (n < 512) {
        const float* w = Ws + 259*256 + (n - 256);
#pragma unroll 8
        for (int j = 0; j < GG; j++) acc = fmaf(gf[j], w[j*256], acc);
    } else {
        const float* w = M1 + 259*128 + (n - 512);
#pragma unroll 8
        for (int j = 0; j < GG; j++) acc = fmaf(gf[j], w[j*128], acc);
    }
    g_bias_eff[b * N1 + n] = g_bias1[n] + acc;
}

// ---------------- build ni = [template | local | pad] -> bf16 hi/lo ------
__global__ void build_ni_kernel(const float* __restrict__ tmpl,
                                const float* __restrict__ pfeat)
{
    __shared__ float srow[KPAD1];
    const int row = blockIdx.x;
    const int tid = threadIdx.x;
    const int b   = row >> 13;

    float w[KK]; int id[KK]; float wsum = 0.f;
#pragma unroll
    for (int k = 0; k < KK; k++) {
        id[k] = g_idx[row*KK+k];
        float d = sqrtf(g_d2[row*KK+k]);
        w[k] = 1.f / (d + 1e-8f);
        wsum += w[k];
    }
    float inv = 1.f / wsum;
#pragma unroll
    for (int k = 0; k < KK; k++) w[k] *= inv;

    const float* pfb = pfeat + (size_t)b * SS * DD;
    float acc = 0.f;
#pragma unroll
    for (int k = 0; k < KK; k++)
        acc = fmaf(w[k], pfb[(size_t)id[k]*DD + tid], acc);

    srow[3 + tid] = acc;
    if (tid < 3)              srow[tid] = tmpl[row*3 + tid];
    if (tid < KPAD1 - NREAL)  srow[NREAL + tid] = 0.f;
    __syncthreads();

    if (tid < KPAD1/4) {                  // 72 * 4 = 288 elems
        __nv_bfloat16 hv[4], lv[4];
#pragma unroll
        for (int q = 0; q < 4; q++)
            bf16split(srow[tid*4 + q], hv[q], lv[q]);
        *(uint2*)&g_ni_hi[(size_t)row * KPAD1 + tid*4] = *(uint2*)hv;
        *(uint2*)&g_ni_lo[(size_t)row * KPAD1 + tid*4] = *(uint2*)lv;
    }
}

// =============== mma.sync compensated bf16 GEMM (128x64, BK=32) ==========
// MODE 0: GEMM1   A=ni (K=288), B=w1t, bias=bias_eff[batch]
//                 -> h1(bf16 hi/lo)/s(f32)/m1(f32)
// MODE 1: GEMM2a  A=h1 (K=256), B=w2t -> fused disp head (atomicAdd to out)
#define A_TILE_B 8192        // 128 rows x 64 bytes
#define B_TILE_B 4096        // 64 rows x 64 bytes

template<int MODE>
__global__ void __launch_bounds__(256, 3) mma_gemm(const float* __restrict__ biasext,
                                                   const float* __restrict__ Wo,
                                                   float* __restrict__ out)
{
    constexpr int KTOT = (MODE == 0) ? KPAD1 : 256;
    constexpr int NCH  = KTOT / 32;

    __shared__ __align__(128) __nv_bfloat16 sAhi[2][A_TILE_B/2];
    __shared__ __align__(128) __nv_bfloat16 sAlo[2][A_TILE_B/2];
    __shared__ __align__(128) __nv_bfloat16 sBhi[2][B_TILE_B/2];
    __shared__ __align__(128) __nv_bfloat16 sBlo[2][B_TILE_B/2];

    const int tid  = threadIdx.x;
    const int wid  = tid >> 5;
    const int lane = tid & 31;
    const int m0 = blockIdx.y * 128;
    const int n0 = blockIdx.x * 64;

    const __nv_bfloat16 *Ahi, *Alo, *Bhi, *Blo;
    const float* bias;
    if (MODE == 0) { Ahi = g_ni_hi; Alo = g_ni_lo; Bhi = g_w1t_hi; Blo = g_w1t_lo;
                     bias = g_bias_eff + (m0 >> 13) * N1; }
    else           { Ahi = g_h1hi;  Alo = g_h1lo;  Bhi = g_w2t_hi; Blo = g_w2t_lo;
                     bias = biasext; }

    const uint32_t uAhi[2] = { smem_to_u32(sAhi[0]), smem_to_u32(sAhi[1]) };
    const uint32_t uAlo[2] = { smem_to_u32(sAlo[0]), smem_to_u32(sAlo[1]) };
    const uint32_t uBhi[2] = { smem_to_u32(sBhi[0]), smem_to_u32(sBhi[1]) };
    const uint32_t uBlo[2] = { smem_to_u32(sBlo[0]), smem_to_u32(sBlo[1]) };

    const int wm = (wid & 3) * 32;       // warp m-offset (4 row-warps)
    const int wn = (wid >> 2) * 32;      // warp n-offset (2 col-warps)

    float acc[2][4][4];
#pragma unroll
    for (int i = 0; i < 2; i++)
#pragma unroll
        for (int j = 0; j < 4; j++)
#pragma unroll
            for (int q = 0; q < 4; q++) acc[i][j][q] = 0.f;

    auto issue_stage = [&](int ch, int buf) {
        const int kc = ch * 32;
#pragma unroll
        for (int t = 0; t < 6; t++) {
            int idx = tid + t * 256;
            if (idx < 1024) {               // A tiles: 2 x 512 chunks
                int half  = idx >> 9;
                int sub   = idx & 511;
                int row   = sub >> 2;
                int chunk = sub & 3;
                const __nv_bfloat16* gp =
                    (half ? Alo : Ahi) + (size_t)(m0 + row) * KTOT + kc + chunk * 8;
                uint32_t off = swz64((uint32_t)(row * 64 + chunk * 16));
                CP_ASYNC16((half ? uAlo[buf] : uAhi[buf]) + off, gp);
            } else {                        // B tiles: 2 x 256 chunks
                int sub   = idx - 1024;
                int half  = sub >> 8;
                int s2    = sub & 255;
                int row   = s2 >> 2;
                int chunk = s2 & 3;
                const __nv_bfloat16* gp =
                    (half ? Blo : Bhi) + (size_t)(n0 + row) * KTOT + kc + chunk * 8;
                uint32_t off = swz64((uint32_t)(row * 64 + chunk * 16));
                CP_ASYNC16((half ? uBlo[buf] : uBhi[buf]) + off, gp);
            }
        }
        CP_COMMIT();
    };

    issue_stage(0, 0);
#pragma unroll 1
    for (int ch = 0; ch < NCH; ch++) {
        const int buf = ch & 1;
        if (ch + 1 < NCH) { issue_stage(ch + 1, buf ^ 1); CP_WAIT(1); }
        else              { CP_WAIT(0); }
        __syncthreads();

        const int lrow = (lane & 7) + ((lane >> 3) & 1) * 8;   // 0..15
        const int lk   = ((lane >> 4) & 1) * 8;                 // 0 or 8
#pragma unroll
        for (int k16 = 0; k16 < 2; k16++) {
            const int kcol = k16 * 16 + lk;
            uint32_t bh[4][2], bl[4][2];
#pragma unroll
            for (int j2 = 0; j2 < 2; j2++) {
                uint32_t off = swz64((uint32_t)((wn + j2*16 + lrow) * 64 + kcol * 2));
                uint32_t r[4];
                ldsm4(r, uBhi[buf] + off);
                bh[j2*2][0] = r[0]; bh[j2*2+1][0] = r[1];
                bh[j2*2][1] = r[2]; bh[j2*2+1][1] = r[3];
                ldsm4(r, uBlo[buf] + off);
                bl[j2*2][0] = r[0]; bl[j2*2+1][0] = r[1];
                bl[j2*2][1] = r[2]; bl[j2*2+1][1] = r[3];
            }
#pragma unroll
            for (int i = 0; i < 2; i++) {
                uint32_t af[4];
                uint32_t off = swz64((uint32_t)((wm + i*16 + lrow) * 64 + kcol * 2));
                ldsm4(af, uAhi[buf] + off);
#pragma unroll
                for (int j = 0; j < 4; j++) {
                    mma_bf16(acc[i][j], af, bh[j]);   // hi*hi
                    mma_bf16(acc[i][j], af, bl[j]);   // hi*lo
                }
                ldsm4(af, uAlo[buf] + off);
#pragma unroll
                for (int j = 0; j < 4; j++)
                    mma_bf16(acc[i][j], af, bh[j]);   // lo*hi
            }
        }
        __syncthreads();
    }

    // ---- epilogue -------------------------------------------------------
    const int g     = lane >> 2;        // 0..7
    const int cpair = (lane & 3) * 2;
#pragma unroll
    for (int i = 0; i < 2; i++) {
#pragma unroll
        for (int half = 0; half < 2; half++) {
            const int r = m0 + wm + i*16 + g + half*8;
            if (MODE == 0) {
#pragma unroll
                for (int j = 0; j < 4; j++) {
                    const int c0 = n0 + wn + j*8 + cpair;
                    const float v0r = acc[i][j][half*2+0] + bias[c0];
                    const float v1r = acc[i][j][half*2+1] + bias[c0+1];
                    if (c0 < 256) {                 // h1: relu -> bf16 hi/lo
                        float v0 = fmaxf(v0r, 0.f), v1 = fmaxf(v1r, 0.f);
                        __nv_bfloat16 h0, l0, h1_, l1_;
                        bf16split(v0, h0, l0); bf16split(v1, h1_, l1_);
                        __nv_bfloat162 ph; ph.x = h0; ph.y = h1_;
                        __nv_bfloat162 pl; pl.x = l0; pl.y = l1_;
                        *(__nv_bfloat162*)&g_h1hi[(size_t)r*256 + c0] = ph;
                        *(__nv_bfloat162*)&g_h1lo[(size_t)r*256 + c0] = pl;
                    } else if (c0 < 512) {          // s: f32
                        float2 p; p.x = v0r; p.y = v1r;
                        *(float2*)&g_s[(size_t)r*256 + (c0-256)] = p;
                    } else {                        // m1: relu f32
                        float2 p; p.x = fmaxf(v0r, 0.f); p.y = fmaxf(v1r, 0.f);
                        *(float2*)&g_m1f[(size_t)r*128 + (c0-512)] = p;
                    }
                }
            } else {
                // h2 = relu(acc+b2)+s, then partial disp = h2 . Wo
                float d0 = 0.f, d1 = 0.f, d2 = 0.f;
#pragma unroll
                for (int j = 0; j < 4; j++) {
                    const int c0 = n0 + wn + j*8 + cpair;
                    float v0 = fmaxf(acc[i][j][half*2+0] + bias[c0],   0.f)
                               + g_s[(size_t)r*256 + c0];
                    float v1 = fmaxf(acc[i][j][half*2+1] + bias[c0+1], 0.f)
                               + g_s[(size_t)r*256 + c0 + 1];
                    d0 = fmaf(v0, Wo[c0*3+0], fmaf(v1, Wo[(c0+1)*3+0], d0));
                    d1 = fmaf(v0, Wo[c0*3+1], fmaf(v1, Wo[(c0+1)*3+1], d1));
                    d2 = fmaf(v0, Wo[c0*3+2], fmaf(v1, Wo[(c0+1)*3+2], d2));
                }
#pragma unroll
                for (int o = 1; o <= 2; o <<= 1) {
                    d0 += __shfl_xor_sync(0xffffffffu, d0, o);
                    d1 += __shfl_xor_sync(0xffffffffu, d1, o);
                    d2 += __shfl_xor_sync(0xffffffffu, d2, o);
                }
                if ((lane & 3) == 0) {
                    atomicAdd(&out[r*3+0], 0.3f * d0);
                    atomicAdd(&out[r*3+1], 0.3f * d1);
                    atomicAdd(&out[r*3+2], 0.3f * d2);
                }
            }
        }
    }
}

// ---------------- GEMM2b + mat head: mat = sigmoid(relu(m1@M2+mb2)@M3+mb3)
__global__ void gemm2b_kernel(const float* __restrict__ M2w,
                              const float* __restrict__ mb2,
                              const float* __restrict__ M3,
                              const float* __restrict__ mb3,
                              float* __restrict__ out)
{
    constexpr int BM=128, BN=64, BK=16, TM=8, TN=4, THREADS=256;
    __shared__ __align__(16) float As[BK*BM];
    __shared__ __align__(16) float Bs[BK*BN];
    const int tid  = threadIdx.x;
    const int row0 = blockIdx.x * BM;
    const int tm0  = (tid / (BN/TN)) * TM;
    const int tn0  = (tid % (BN/TN)) * TN;
    float4 pa[2], pb[1];

    auto loadg = [&](int k0) {
#pragma unroll
        for (int i = 0; i < 2; i++) {
            int idx = tid + i*THREADS; int m = idx / 4; int kv = idx % 4;
            pa[i] = *(const float4*)(g_m1f + (size_t)(row0+m)*128 + k0 + kv*4);
        }
        { int kr = tid / 16; int nv = tid % 16;
          pb[0] = *(const float4*)(M2w + (size_t)(k0 + kr)*64 + nv*4); }
    };
    auto stage = [&]() {
#pragma unroll
        for (int i = 0; i < 2; i++) {
            int idx = tid + i*THREADS; int m = idx / 4; int kv = idx % 4;
            As[(kv*4+0)*BM+m]=pa[i].x; As[(kv*4+1)*BM+m]=pa[i].y;
            As[(kv*4+2)*BM+m]=pa[i].z; As[(kv*4+3)*BM+m]=pa[i].w;
        }
        { int kr = tid / 16; int nv = tid % 16;
          *(float4*)&Bs[kr*BN + nv*4] = pb[0]; }
    };

    float acc[TM][TN];
#pragma unroll
    for (int i=0;i<TM;i++)
#pragma unroll
        for (int j=0;j<TN;j++) acc[i][j]=0.f;

    loadg(0);
#pragma unroll 1
    for (int t = 0; t < 128/BK; t++) {
        __syncthreads(); stage(); __syncthreads();
        if (t+1 < 128/BK) loadg((t+1)*BK);
#pragma unroll
        for (int kk = 0; kk < BK; kk++) {
            float af[TM], bf[TN];
#pragma unroll
            for (int i=0;i<TM/4;i++) *(float4*)&af[i*4] = *(const float4*)&As[kk*BM+tm0+i*4];
            *(float4*)&bf[0] = *(const float4*)&Bs[kk*BN+tn0];
#pragma unroll
            for (int i=0;i<TM;i++)
#pragma unroll
                for (int j=0;j<TN;j++) acc[i][j] = fmaf(af[i], bf[j], acc[i][j]);
        }
    }

    // mat head: row's 64 cols live in the 16 threads sharing tid/16
    float mv[TM];
#pragma unroll
    for (int i=0;i<TM;i++) {
        float m = 0.f;
#pragma unroll
        for (int j=0;j<TN;j++) {
            int n = tn0 + j;
            m = fmaf(fmaxf(acc[i][j] + mb2[n], 0.f), M3[n], m);
        }
        mv[i] = m;
    }
#pragma unroll
    for (int o = 1; o <= 8; o <<= 1)
#pragma unroll
        for (int i=0;i<TM;i++)
            mv[i] += __shfl_xor_sync(0xffffffffu, mv[i], o);
    if ((tid & 15) == 0) {
        const float b3 = mb3[0];
#pragma unroll
        for (int i=0;i<TM;i++) {
            float x = mv[i] + b3;
            out[MATOFF + row0 + tm0 + i] = 1.f / (1.f + expf(-x));
        }
    }
}

// --------------------------------- launch --------------------------------
extern "C" void kernel_launch(void* const* d_in, const int* in_sizes, int n_in,
                              void* d_out, int out_size)
{
    const float* tmpl  = (const float*)d_in[0];
    const float* surf  = (const float*)d_in[1];
    const float* gfeat = (const float*)d_in[2];
    const float* pfeat = (const float*)d_in[3];
    const float* W1 = (const float*)d_in[4];
    const float* b1 = (const float*)d_in[5];
    const float* W2 = (const float*)d_in[6];
    const float* b2 = (const float*)d_in[7];
    const float* Ws = (const float*)d_in[8];
    const float* bs = (const float*)d_in[9];
    const float* Wo = (const float*)d_in[10];
    const float* bo = (const float*)d_in[11];
    const float* M1 = (const float*)d_in[12];
    const float* mb1 = (const float*)d_in[13];
    const float* M2 = (const float*)d_in[14];
    const float* mb2 = (const float*)d_in[15];
    const float* M3 = (const float*)d_in[16];
    const float* mb3 = (const float*)d_in[17];
    float* out = (float*)d_out;

    knn_kernel<<<dim3(TT/128, BB), 128>>>(tmpl, surf);
    prepack_kernel<<<(N1*KPAD1 + 255)/256, 256>>>(W1, Ws, M1, b1, bs, mb1, W2, bo, out);
    gvec_kernel<<<dim3(BB, N1/128), 128>>>(gfeat, W1, Ws, M1);
    build_ni_kernel<<<ROWS, 256>>>(tmpl, pfeat);

    // GEMM1: [32768 x 288] @ [288 x 640] (compensated bf16 mma.sync)
    mma_gemm<0><<<dim3(N1/64, ROWS/128), 256>>>(nullptr, nullptr, nullptr);
    // GEMM2a + disp head: h2 = relu(h1@W2+b2)+s ; atomicAdd 0.3*(h2.Wo)
    mma_gemm<1><<<dim3(256/64, ROWS/128), 256>>>(b2, Wo, out);
    // GEMM2b + mat head
    gemm2b_kernel<<<ROWS/128, 256>>>(M2, mb2, M3, mb3, out);
}

// round 8
// speedup vs baseline: 2.9523x; 1.1202x over previous
#include <cuda_runtime.h>
#include <cuda_bf16.h>
#include <math.h>
#include <float.h>
#include <stdint.h>

// Problem constants
#define BB 4
#define TT 8192
#define SS 4096
#define DD 256
#define GG 512
#define KK 8
#define ROWS (BB*TT)        // 32768
#define NREAL 259           // template(3) + local(256); global folded into bias
#define KPAD1 288           // 9 * 32
#define N1 640              // 256 (W1) + 256 (Ws) + 128 (M1)
#define MATOFF (ROWS*3)     // offset of mat in out

// ---------------- scratch (device globals; no allocation) ----------------
__device__ __align__(128) int   g_idx[ROWS * KK];
__device__ __align__(128) float g_d2 [ROWS * KK];
__device__ __align__(128) __nv_bfloat16 g_ni_hi[(size_t)ROWS * KPAD1];
__device__ __align__(128) __nv_bfloat16 g_ni_lo[(size_t)ROWS * KPAD1];
__device__ __align__(128) __nv_bfloat16 g_w1t_hi[N1 * KPAD1];
__device__ __align__(128) __nv_bfloat16 g_w1t_lo[N1 * KPAD1];
__device__ __align__(128) __nv_bfloat16 g_w2t_hi[256 * 256];
__device__ __align__(128) __nv_bfloat16 g_w2t_lo[256 * 256];
__device__ __align__(128) float g_bias1[N1];
__device__ __align__(128) float g_bias_eff[BB * N1];   // bias1 + gfeat@W_global
__device__ __align__(128) __nv_bfloat16 g_h1hi[(size_t)ROWS * 256];
__device__ __align__(128) float g_s  [(size_t)ROWS * 256];
__device__ __align__(128) float g_m1f[(size_t)ROWS * 128];

// =================== helpers =============================================
__device__ __forceinline__ uint32_t smem_to_u32(const void* p) {
    uint32_t a;
    asm("{ .reg .u64 t; cvta.to.shared.u64 t, %1; cvt.u32.u64 %0, t; }" : "=r"(a) : "l"(p));
    return a;
}
__device__ __forceinline__ void ldsm4(uint32_t* r, uint32_t addr) {
    asm volatile("ldmatrix.sync.aligned.m8n8.x4.shared.b16 {%0,%1,%2,%3}, [%4];"
        : "=r"(r[0]), "=r"(r[1]), "=r"(r[2]), "=r"(r[3]) : "r"(addr));
}
__device__ __forceinline__ void mma_bf16(float* c, const uint32_t* a, const uint32_t* b) {
    asm volatile("mma.sync.aligned.m16n8k16.row.col.f32.bf16.bf16.f32 "
        "{%0,%1,%2,%3}, {%4,%5,%6,%7}, {%8,%9}, {%0,%1,%2,%3};"
        : "+f"(c[0]), "+f"(c[1]), "+f"(c[2]), "+f"(c[3])
        : "r"(a[0]), "r"(a[1]), "r"(a[2]), "r"(a[3]), "r"(b[0]), "r"(b[1]));
}
#define CP_ASYNC16(dst, src) \
    asm volatile("cp.async.cg.shared.global [%0], [%1], 16;" :: "r"(dst), "l"(src))
#define CP_COMMIT()  asm volatile("cp.async.commit_group;" ::: "memory")
#define CP_WAIT(n)   asm volatile("cp.async.wait_group %0;" :: "n"(n) : "memory")

// swizzle for tiles with 64-byte rows (32 bf16)
__device__ __forceinline__ uint32_t swz64(uint32_t off) {
    return off ^ (((off >> 7) & 3u) << 4);
}
__device__ __forceinline__ void bf16split(float v, __nv_bfloat16& h, __nv_bfloat16& l) {
    h = __float2bfloat16(v);
    l = __float2bfloat16(v - __bfloat162float(h));
}

// ---------------- KNN: top-8 nearest surf points per template point ------
__global__ void knn_kernel(const float* __restrict__ tmpl,
                           const float* __restrict__ surf)
{
    __shared__ float4 ss[2048];
    const int b   = blockIdx.y;
    const int t   = blockIdx.x * 128 + threadIdx.x;
    const int row = b * TT + t;

    const float tx = tmpl[row*3+0];
    const float ty = tmpl[row*3+1];
    const float tz = tmpl[row*3+2];

    float bd[KK]; int bi[KK];
#pragma unroll
    for (int q = 0; q < KK; q++) { bd[q] = FLT_MAX; bi[q] = 0; }
    const float* sb = surf + (size_t)b * SS * 3;

    for (int tile = 0; tile < 2; tile++) {
        __syncthreads();
        for (int i = threadIdx.x; i < 2048; i += 128) {
            int sp = tile * 2048 + i;
            ss[i] = make_float4(sb[sp*3+0], sb[sp*3+1], sb[sp*3+2], 0.f);
        }
        __syncthreads();
#pragma unroll 4
        for (int j = 0; j < 2048; j++) {
            float4 p = ss[j];
            float dx = tx - p.x, dy = ty - p.y, dz = tz - p.z;
            float d2 = fmaf(dx, dx, fmaf(dy, dy, dz*dz));
            if (d2 < bd[KK-1]) {
                float v = d2; int vi = tile * 2048 + j;
#pragma unroll
                for (int q = 0; q < KK; q++) {
                    if (v < bd[q]) {
                        float tv = bd[q]; int ti = bi[q];
                        bd[q] = v; bi[q] = vi; v = tv; vi = ti;
                    }
                }
            }
        }
    }
#pragma unroll
    for (int q = 0; q < KK; q++) {
        g_d2 [row*KK+q] = bd[q];
        g_idx[row*KK+q] = bi[q];
    }
}

// ---------------- prepack + out disp init --------------------------------
__global__ void prepack_kernel(const float* __restrict__ W1,
                               const float* __restrict__ Ws,
                               const float* __restrict__ M1,
                               const float* __restrict__ b1,
                               const float* __restrict__ bs,
                               const float* __restrict__ mb1,
                               const float* __restrict__ W2,
                               const float* __restrict__ bo,
                               float* __restrict__ out)
{
    int idx = blockIdx.x * 256 + threadIdx.x;
    if (idx < N1 * KPAD1) {
        int n = idx / KPAD1, k = idx % KPAD1;
        float v = 0.f;
        if (k < NREAL) {                   // orig input index == k for k<259
            if (n < 256)       v = W1[k*256 + n];
            else if (n < 512)  v = Ws[k*256 + (n-256)];
            else               v = M1[k*128 + (n-512)];
        }
        __nv_bfloat16 h, l; bf16split(v, h, l);
        g_w1t_hi[idx] = h; g_w1t_lo[idx] = l;
    }
    if (idx < 256 * 256) {
        int n = idx / 256, k = idx % 256;
        __nv_bfloat16 h, l; bf16split(W2[k*256 + n], h, l);
        g_w2t_hi[idx] = h; g_w2t_lo[idx] = l;
    }
    if (idx < N1) {
        float bv;
        if (idx < 256)       bv = b1[idx];
        else if (idx < 512)  bv = bs[idx-256];
        else                 bv = mb1[idx-512];
        g_bias1[idx] = bv;
    }
    if (idx < MATOFF)                      // init disp = 0.3 * bo
        out[idx] = bo[idx % 3] * 0.3f;
}

// ---------------- fold global_feat into bias (fp32 exact) ----------------
__global__ void gvec_kernel(const float* __restrict__ gfeat,
                            const float* __restrict__ W1,
                            const float* __restrict__ Ws,
                            const float* __restrict__ M1)
{
    const int b = blockIdx.x;
    const int n = blockIdx.y * 128 + threadIdx.x;
    const float* gf = gfeat + b * GG;
    float acc = 0.f;
    if (n < 256) {
        const float* w = W1 + 259*256 + n;
#pragma unroll 8
        for (int j = 0; j < GG; j++) acc = fmaf(gf[j], w[j*256], acc);
    } else if (n < 512) {
        const float* w = Ws + 259*256 + (n - 256);
#pragma unroll 8
        for (int j = 0; j < GG; j++) acc = fmaf(gf[j], w[j*256], acc);
    } else {
        const float* w = M1 + 259*128 + (n - 512);
#pragma unroll 8
        for (int j = 0; j < GG; j++) acc = fmaf(gf[j], w[j*128], acc);
    }
    g_bias_eff[b * N1 + n] = g_bias1[n] + acc;
}

// ---------------- build ni: 4 rows/block, float4 gathers -----------------
__global__ void __launch_bounds__(256) build_ni_kernel(
    const float* __restrict__ tmpl,
    const float* __restrict__ pfeat)
{
    __shared__ float sw [4][KK];
    __shared__ int   sid[4][KK];
    __shared__ float srow[4][KPAD1];
    const int tid  = threadIdx.x;
    const int row0 = blockIdx.x * 4;

    // phase 1: 32 threads compute normalized weights (8 lanes per row)
    if (tid < 32) {
        int rloc = tid >> 3, k = tid & 7;
        int row = row0 + rloc;
        sid[rloc][k] = g_idx[row*KK + k];
        float d = sqrtf(g_d2[row*KK + k]);
        float w = 1.f / (d + 1e-8f);
        float s = w;
#pragma unroll
        for (int o = 1; o < 8; o <<= 1)
            s += __shfl_xor_sync(0xffffffffu, s, o);
        sw[rloc][k] = w / s;
    }
    if (tid >= 32 && tid < 44) {            // template cols
        int q = tid - 32; int rloc = q / 3, c = q % 3;
        srow[rloc][c] = tmpl[(row0 + rloc)*3 + c];
    }
    if (tid >= 64 && tid < 64 + 4*(KPAD1 - NREAL)) {   // zero pad (29 cols x 4)
        int q = tid - 64; int rloc = q / (KPAD1 - NREAL), c = q % (KPAD1 - NREAL);
        srow[rloc][NREAL + c] = 0.f;
    }
    __syncthreads();

    // phase 2: coalesced float4 gather, 64 threads per row
    {
        const int rloc = tid >> 6, c4 = tid & 63;
        const int b = (row0 + rloc) >> 13;
        const float* pfb = pfeat + (size_t)b * SS * DD;
        float4 acc = make_float4(0.f, 0.f, 0.f, 0.f);
#pragma unroll
        for (int k = 0; k < KK; k++) {
            const float w = sw[rloc][k];
            const float4 v = *(const float4*)(pfb + (size_t)sid[rloc][k]*DD + c4*4);
            acc.x = fmaf(w, v.x, acc.x);
            acc.y = fmaf(w, v.y, acc.y);
            acc.z = fmaf(w, v.z, acc.z);
            acc.w = fmaf(w, v.w, acc.w);
        }
        srow[rloc][3 + c4*4 + 0] = acc.x;
        srow[rloc][3 + c4*4 + 1] = acc.y;
        srow[rloc][3 + c4*4 + 2] = acc.z;
        srow[rloc][3 + c4*4 + 3] = acc.w;
    }
    __syncthreads();

    // phase 3: pack to bf16 hi/lo, 8B stores
    for (int p = tid; p < 4 * (KPAD1/4); p += 256) {
        int rloc = p / (KPAD1/4), q = p % (KPAD1/4);
        __nv_bfloat16 hv[4], lv[4];
#pragma unroll
        for (int s = 0; s < 4; s++)
            bf16split(srow[rloc][q*4 + s], hv[s], lv[s]);
        size_t base = (size_t)(row0 + rloc) * KPAD1 + q*4;
        *(uint2*)&g_ni_hi[base] = *(uint2*)hv;
        *(uint2*)&g_ni_lo[base] = *(uint2*)lv;
    }
}

// =============== mma.sync compensated bf16 GEMM (128x64, BK=32) ==========
// MODE 0: GEMM1   A=ni hi/lo (K=288), B=w1t hi/lo, bias=bias_eff[batch]
//                 -> h1(bf16)/s(f32)/m1(f32)        [3-term compensation]
// MODE 1: GEMM2a  A=h1 bf16 (K=256), B=w2t hi/lo -> fused disp head
//                 [2-term: A*Bhi + A*Blo]
#define A_TILE_B 8192        // 128 rows x 64 bytes
#define B_TILE_B 4096        // 64 rows x 64 bytes

template<int MODE>
__global__ void __launch_bounds__(256, 3) mma_gemm(const float* __restrict__ biasext,
                                                   const float* __restrict__ Wo,
                                                   float* __restrict__ out)
{
    constexpr int  KTOT = (MODE == 0) ? KPAD1 : 256;
    constexpr int  NCH  = KTOT / 32;
    constexpr bool ALO  = (MODE == 0);

    __shared__ __align__(128) __nv_bfloat16 sAhi[2][A_TILE_B/2];
    __shared__ __align__(128) __nv_bfloat16 sAlo[2][A_TILE_B/2];
    __shared__ __align__(128) __nv_bfloat16 sBhi[2][B_TILE_B/2];
    __shared__ __align__(128) __nv_bfloat16 sBlo[2][B_TILE_B/2];

    const int tid  = threadIdx.x;
    const int wid  = tid >> 5;
    const int lane = tid & 31;
    const int m0 = blockIdx.y * 128;
    const int n0 = blockIdx.x * 64;

    const __nv_bfloat16 *Ahi, *Alo, *Bhi, *Blo;
    const float* bias;
    if (MODE == 0) { Ahi = g_ni_hi; Alo = g_ni_lo; Bhi = g_w1t_hi; Blo = g_w1t_lo;
                     bias = g_bias_eff + (m0 >> 13) * N1; }
    else           { Ahi = g_h1hi;  Alo = g_h1hi;  Bhi = g_w2t_hi; Blo = g_w2t_lo;
                     bias = biasext; }

    const uint32_t uAhi[2] = { smem_to_u32(sAhi[0]), smem_to_u32(sAhi[1]) };
    const uint32_t uAlo[2] = { smem_to_u32(sAlo[0]), smem_to_u32(sAlo[1]) };
    const uint32_t uBhi[2] = { smem_to_u32(sBhi[0]), smem_to_u32(sBhi[1]) };
    const uint32_t uBlo[2] = { smem_to_u32(sBlo[0]), smem_to_u32(sBlo[1]) };

    const int wm = (wid & 3) * 32;       // warp m-offset (4 row-warps)
    const int wn = (wid >> 2) * 32;      // warp n-offset (2 col-warps)

    float acc[2][4][4];
#pragma unroll
    for (int i = 0; i < 2; i++)
#pragma unroll
        for (int j = 0; j < 4; j++)
#pragma unroll
            for (int q = 0; q < 4; q++) acc[i][j][q] = 0.f;

    auto issue_stage = [&](int ch, int buf) {
        const int kc = ch * 32;
        constexpr int NLOAD = ALO ? 6 : 4;     // 16B chunks / 256 threads
        constexpr int ACH   = ALO ? 1024 : 512;
#pragma unroll
        for (int t = 0; t < NLOAD; t++) {
            int idx = tid + t * 256;
            if (idx < ACH) {                // A tiles
                int half  = ALO ? (idx >> 9) : 0;
                int sub   = idx & 511;
                int row   = sub >> 2;
                int chunk = sub & 3;
                const __nv_bfloat16* gp =
                    (half ? Alo : Ahi) + (size_t)(m0 + row) * KTOT + kc + chunk * 8;
                uint32_t off = swz64((uint32_t)(row * 64 + chunk * 16));
                CP_ASYNC16((half ? uAlo[buf] : uAhi[buf]) + off, gp);
            } else {                        // B tiles: hi then lo, 256 each
                int sub   = idx - ACH;
                int half  = sub >> 8;
                int s2    = sub & 255;
                int row   = s2 >> 2;
                int chunk = s2 & 3;
                const __nv_bfloat16* gp =
                    (half ? Blo : Bhi) + (size_t)(n0 + row) * KTOT + kc + chunk * 8;
                uint32_t off = swz64((uint32_t)(row * 64 + chunk * 16));
                CP_ASYNC16((half ? uBlo[buf] : uBhi[buf]) + off, gp);
            }
        }
        CP_COMMIT();
    };

    issue_stage(0, 0);
#pragma unroll 1
    for (int ch = 0; ch < NCH; ch++) {
        const int buf = ch & 1;
        if (ch + 1 < NCH) { issue_stage(ch + 1, buf ^ 1); CP_WAIT(1); }
        else              { CP_WAIT(0); }
        __syncthreads();

        const int lrow = (lane & 7) + ((lane >> 3) & 1) * 8;   // 0..15
        const int lk   = ((lane >> 4) & 1) * 8;                 // 0 or 8
#pragma unroll
        for (int k16 = 0; k16 < 2; k16++) {
            const int kcol = k16 * 16 + lk;
            uint32_t bh[4][2], bl[4][2];
#pragma unroll
            for (int j2 = 0; j2 < 2; j2++) {
                uint32_t off = swz64((uint32_t)((wn + j2*16 + lrow) * 64 + kcol * 2));
                uint32_t r[4];
                ldsm4(r, uBhi[buf] + off);
                bh[j2*2][0] = r[0]; bh[j2*2+1][0] = r[1];
                bh[j2*2][1] = r[2]; bh[j2*2+1][1] = r[3];
                ldsm4(r, uBlo[buf] + off);
                bl[j2*2][0] = r[0]; bl[j2*2+1][0] = r[1];
                bl[j2*2][1] = r[2]; bl[j2*2+1][1] = r[3];
            }
#pragma unroll
            for (int i = 0; i < 2; i++) {
                uint32_t af[4];
                uint32_t off = swz64((uint32_t)((wm + i*16 + lrow) * 64 + kcol * 2));
                ldsm4(af, uAhi[buf] + off);
#pragma unroll
                for (int j = 0; j < 4; j++) {
                    mma_bf16(acc[i][j], af, bh[j]);   // hi*hi
                    mma_bf16(acc[i][j], af, bl[j]);   // hi*lo
                }
                if (ALO) {
                    ldsm4(af, uAlo[buf] + off);
#pragma unroll
                    for (int j = 0; j < 4; j++)
                        mma_bf16(acc[i][j], af, bh[j]);   // lo*hi
                }
            }
        }
        __syncthreads();
    }

    // ---- epilogue -------------------------------------------------------
    const int g     = lane >> 2;        // 0..7
    const int cpair = (lane & 3) * 2;
#pragma unroll
    for (int i = 0; i < 2; i++) {
#pragma unroll
        for (int half = 0; half < 2; half++) {
            const int r = m0 + wm + i*16 + g + half*8;
            if (MODE == 0) {
#pragma unroll
                for (int j = 0; j < 4; j++) {
                    const int c0 = n0 + wn + j*8 + cpair;
                    const float v0r = acc[i][j][half*2+0] + bias[c0];
                    const float v1r = acc[i][j][half*2+1] + bias[c0+1];
                    if (c0 < 256) {                 // h1: relu -> bf16
                        __nv_bfloat162 ph;
                        ph.x = __float2bfloat16(fmaxf(v0r, 0.f));
                        ph.y = __float2bfloat16(fmaxf(v1r, 0.f));
                        *(__nv_bfloat162*)&g_h1hi[(size_t)r*256 + c0] = ph;
                    } else if (c0 < 512) {          // s: f32
                        float2 p; p.x = v0r; p.y = v1r;
                        *(float2*)&g_s[(size_t)r*256 + (c0-256)] = p;
                    } else {                        // m1: relu f32
                        float2 p; p.x = fmaxf(v0r, 0.f); p.y = fmaxf(v1r, 0.f);
                        *(float2*)&g_m1f[(size_t)r*128 + (c0-512)] = p;
                    }
                }
            } else {
                // h2 = relu(acc+b2)+s, then partial disp = h2 . Wo
                float d0 = 0.f, d1 = 0.f, d2 = 0.f;
#pragma unroll
                for (int j = 0; j < 4; j++) {
                    const int c0 = n0 + wn + j*8 + cpair;
                    float v0 = fmaxf(acc[i][j][half*2+0] + bias[c0],   0.f)
                               + g_s[(size_t)r*256 + c0];
                    float v1 = fmaxf(acc[i][j][half*2+1] + bias[c0+1], 0.f)
                               + g_s[(size_t)r*256 + c0 + 1];
                    d0 = fmaf(v0, Wo[c0*3+0], fmaf(v1, Wo[(c0+1)*3+0], d0));
                    d1 = fmaf(v0, Wo[c0*3+1], fmaf(v1, Wo[(c0+1)*3+1], d1));
                    d2 = fmaf(v0, Wo[c0*3+2], fmaf(v1, Wo[(c0+1)*3+2], d2));
                }
#pragma unroll
                for (int o = 1; o <= 2; o <<= 1) {
                    d0 += __shfl_xor_sync(0xffffffffu, d0, o);
                    d1 += __shfl_xor_sync(0xffffffffu, d1, o);
                    d2 += __shfl_xor_sync(0xffffffffu, d2, o);
                }
                if ((lane & 3) == 0) {
                    atomicAdd(&out[r*3+0], 0.3f * d0);
                    atomicAdd(&out[r*3+1], 0.3f * d1);
                    atomicAdd(&out[r*3+2], 0.3f * d2);
                }
            }
        }
    }
}

// ---------------- GEMM2b + mat head: mat = sigmoid(relu(m1@M2+mb2)@M3+mb3)
__global__ void gemm2b_kernel(const float* __restrict__ M2w,
                              const float* __restrict__ mb2,
                              const float* __restrict__ M3,
                              const float* __restrict__ mb3,
                              float* __restrict__ out)
{
    constexpr int BM=128, BN=64, BK=16, TM=8, TN=4, THREADS=256;
    __shared__ __align__(16) float As[BK*BM];
    __shared__ __align__(16) float Bs[BK*BN];
    const int tid  = threadIdx.x;
    const int row0 = blockIdx.x * BM;
    const int tm0  = (tid / (BN/TN)) * TM;
    const int tn0  = (tid % (BN/TN)) * TN;
    float4 pa[2], pb[1];

    auto loadg = [&](int k0) {
#pragma unroll
        for (int i = 0; i < 2; i++) {
            int idx = tid + i*THREADS; int m = idx / 4; int kv = idx % 4;
            pa[i] = *(const float4*)(g_m1f + (size_t)(row0+m)*128 + k0 + kv*4);
        }
        { int kr = tid / 16; int nv = tid % 16;
          pb[0] = *(const float4*)(M2w + (size_t)(k0 + kr)*64 + nv*4); }
    };
    auto stage = [&]() {
#pragma unroll
        for (int i = 0; i < 2; i++) {
            int idx = tid + i*THREADS; int m = idx / 4; int kv = idx % 4;
            As[(kv*4+0)*BM+m]=pa[i].x; As[(kv*4+1)*BM+m]=pa[i].y;
            As[(kv*4+2)*BM+m]=pa[i].z; As[(kv*4+3)*BM+m]=pa[i].w;
        }
        { int kr = tid / 16; int nv = tid % 16;
          *(float4*)&Bs[kr*BN + nv*4] = pb[0]; }
    };

    float acc[TM][TN];
#pragma unroll
    for (int i=0;i<TM;i++)
#pragma unroll
        for (int j=0;j<TN;j++) acc[i][j]=0.f;

    loadg(0);
#pragma unroll 1
    for (int t = 0; t < 128/BK; t++) {
        __syncthreads(); stage(); __syncthreads();
        if (t+1 < 128/BK) loadg((t+1)*BK);
#pragma unroll
        for (int kk = 0; kk < BK; kk++) {
            float af[TM], bf[TN];
#pragma unroll
            for (int i=0;i<TM/4;i++) *(float4*)&af[i*4] = *(const float4*)&As[kk*BM+tm0+i*4];
            *(float4*)&bf[0] = *(const float4*)&Bs[kk*BN+tn0];
#pragma unroll
            for (int i=0;i<TM;i++)
#pragma unroll
                for (int j=0;j<TN;j++) acc[i][j] = fmaf(af[i], bf[j], acc[i][j]);
        }
    }

    // mat head: row's 64 cols live in the 16 threads sharing tid/16
    float mv[TM];
#pragma unroll
    for (int i=0;i<TM;i++) {
        float m = 0.f;
#pragma unroll
        for (int j=0;j<TN;j++) {
            int n = tn0 + j;
            m = fmaf(fmaxf(acc[i][j] + mb2[n], 0.f), M3[n], m);
        }
        mv[i] = m;
    }
#pragma unroll
    for (int o = 1; o <= 8; o <<= 1)
#pragma unroll
        for (int i=0;i<TM;i++)
            mv[i] += __shfl_xor_sync(0xffffffffu, mv[i], o);
    if ((tid & 15) == 0) {
        const float b3 = mb3[0];
#pragma unroll
        for (int i=0;i<TM;i++) {
            float x = mv[i] + b3;
            out[MATOFF + row0 + tm0 + i] = 1.f / (1.f + expf(-x));
        }
    }
}

// --------------------------------- launch --------------------------------
extern "C" void kernel_launch(void* const* d_in, const int* in_sizes, int n_in,
                              void* d_out, int out_size)
{
    const float* tmpl  = (const float*)d_in[0];
    const float* surf  = (const float*)d_in[1];
    const float* gfeat = (const float*)d_in[2];
    const float* pfeat = (const float*)d_in[3];
    const float* W1 = (const float*)d_in[4];
    const float* b1 = (const float*)d_in[5];
    const float* W2 = (const float*)d_in[6];
    const float* b2 = (const float*)d_in[7];
    const float* Ws = (const float*)d_in[8];
    const float* bs = (const float*)d_in[9];
    const float* Wo = (const float*)d_in[10];
    const float* bo = (const float*)d_in[11];
    const float* M1 = (const float*)d_in[12];
    const float* mb1 = (const float*)d_in[13];
    const float* M2 = (const float*)d_in[14];
    const float* mb2 = (const float*)d_in[15];
    const float* M3 = (const float*)d_in[16];
    const float* mb3 = (const float*)d_in[17];
    float* out = (float*)d_out;

    knn_kernel<<<dim3(TT/128, BB), 128>>>(tmpl, surf);
    prepack_kernel<<<(N1*KPAD1 + 255)/256, 256>>>(W1, Ws, M1, b1, bs, mb1, W2, bo, out);
    gvec_kernel<<<dim3(BB, N1/128), 128>>>(gfeat, W1, Ws, M1);
    build_ni_kernel<<<ROWS/4, 256>>>(tmpl, pfeat);

    // GEMM1: [32768 x 288] @ [288 x 640] (compensated bf16 mma.sync)
    mma_gemm<0><<<dim3(N1/64, ROWS/128), 256>>>(nullptr, nullptr, nullptr);
    // GEMM2a + disp head: h2 = relu(h1@W2+b2)+s ; atomicAdd 0.3*(h2.Wo)
    mma_gemm<1><<<dim3(256/64, ROWS/128), 256>>>(b2, Wo, out);
    // GEMM2b + mat head
    gemm2b_kernel<<<ROWS/128, 256>>>(M2, mb2, M3, mb3, out);
}